// round 10
// baseline (speedup 1.0000x reference)
#include <cuda_runtime.h>
#include <cstdint>

#define BB 2
#define SS 2048
#define DD 1024
#define HH 16
#define DHH 64
#define BHH 32
#define MM 4096

// ---------------- scratch ----------------
__device__ float g_Qu[(size_t)BHH * SS * DHH];
__device__ float g_Qv[(size_t)BHH * SS * DHH];
__device__ float g_Kh[(size_t)BHH * SS * DHH];
__device__ float g_Vh[(size_t)BHH * SS * DHH];
__device__ float g_VhT[(size_t)BHH * SS * DHH];   // [bh][d][s]
__device__ float g_Ph[(size_t)BHH * SS * DHH];
__device__ float g_S1[(size_t)BHH * SS * SS];     // PRE-SHIFTED pos scores
__device__ float g_O [(size_t)MM * DD];

// ---------------- mma.sync tf32 helpers ----------------
__device__ __forceinline__ uint32_t f2tf32(float f) {
    uint32_t t;
    asm("cvt.rna.tf32.f32 %0, %1;" : "=r"(t) : "f"(f));
    return t;
}
__device__ __forceinline__ void mma_tf32(float c[4], const uint32_t a[4], const uint32_t b[2]) {
    asm volatile(
        "mma.sync.aligned.m16n8k8.row.col.f32.tf32.tf32.f32 "
        "{%0,%1,%2,%3}, {%4,%5,%6,%7}, {%8,%9}, {%0,%1,%2,%3};"
        : "+f"(c[0]), "+f"(c[1]), "+f"(c[2]), "+f"(c[3])
        : "r"(a[0]), "r"(a[1]), "r"(a[2]), "r"(a[3]), "r"(b[0]), "r"(b[1]));
}
__device__ __forceinline__ uint2 pack_tf32(float lo, float hi) {
    uint2 u; u.x = f2tf32(lo); u.y = f2tf32(hi); return u;
}

// ================= paired loaders / STS.64 stores (256-thread) =================
__device__ __forceinline__ void loadA_p(const float* __restrict__ src, int lda,
                                        int kc, int tid, float4* pa) {
#pragma unroll
    for (int j = 0; j < 2; ++j) {
        int i2 = tid + j * 256;
        int c4 = i2 & 7, rr = i2 >> 3;
        int r = ((rr >> 3) << 4) + (rr & 7);
        pa[2 * j]     = *(const float4*)(src + (size_t)r * lda + kc + c4 * 4);
        pa[2 * j + 1] = *(const float4*)(src + (size_t)(r + 8) * lda + kc + c4 * 4);
    }
}
__device__ __forceinline__ void storeA_p(const float4* pa, uint32_t* dst, int tid) {
    uint2* d2 = (uint2*)dst;
#pragma unroll
    for (int j = 0; j < 2; ++j) {
        int i2 = tid + j * 256;
        int c4 = i2 & 7, rr = i2 >> 3;
        int r = ((rr >> 3) << 4) + (rr & 7);
        int kstep = c4 >> 1, mg = r >> 4, laneb = (r & 7) * 4, rh = c4 & 1;
        const float lo[4] = {pa[2 * j].x, pa[2 * j].y, pa[2 * j].z, pa[2 * j].w};
        const float hi[4] = {pa[2 * j + 1].x, pa[2 * j + 1].y, pa[2 * j + 1].z, pa[2 * j + 1].w};
#pragma unroll
        for (int e = 0; e < 4; ++e)
            d2[(((kstep * 8 + mg) * 32) + laneb + e) * 2 + rh] = pack_tf32(lo[e], hi[e]);
    }
}
__device__ __forceinline__ void loadB_p(const float* __restrict__ src, int ldb,
                                        int kc, int tid, float4* pb) {
#pragma unroll
    for (int j = 0; j < 2; ++j) {
        int i2 = tid + j * 256;
        int s4 = i2 & 3, r = i2 >> 2;
        pb[2 * j]     = *(const float4*)(src + (size_t)r * ldb + kc + s4 * 8);
        pb[2 * j + 1] = *(const float4*)(src + (size_t)r * ldb + kc + s4 * 8 + 4);
    }
}
__device__ __forceinline__ void storeB_p(const float4* pb, uint32_t* dst, int tid) {
    uint2* d2 = (uint2*)dst;
#pragma unroll
    for (int j = 0; j < 2; ++j) {
        int i2 = tid + j * 256;
        int s4 = i2 & 3, r = i2 >> 2;
        int ng = r >> 3, laneb = (r & 7) * 4;
        const float lo[4] = {pb[2 * j].x, pb[2 * j].y, pb[2 * j].z, pb[2 * j].w};
        const float hi[4] = {pb[2 * j + 1].x, pb[2 * j + 1].y, pb[2 * j + 1].z, pb[2 * j + 1].w};
#pragma unroll
        for (int e = 0; e < 4; ++e)
            d2[(s4 * 16 + ng) * 32 + laneb + e] = pack_tf32(lo[e], hi[e]);
    }
}

// ================= tf32 GEMM mainloop core (NT=128, 256 threads) =================
// C[128x128] = A[128,K] . B[128,K]^T, result left in acc registers.
// Thread (wm=wid%4, wn=wid/4): rows wm*32+mf*16+{gr, gr+8}, cols wn*64+nf*8+{gc, gc+1}.
__device__ __forceinline__ void gemm128_core(const float* __restrict__ A, int lda,
                                             const float* __restrict__ B, int ldb,
                                             int K, char* sm, float acc[2][8][4]) {
    const int tid  = threadIdx.x;
    const int wid  = tid >> 5;
    const int lane = tid & 31;
    const int wm   = wid & 3;
    const int wn   = wid >> 2;
    const int mgb  = wm * 2;
    const int ngb  = wn * 8;

    uint32_t* s = (uint32_t*)sm;
#pragma unroll
    for (int i = 0; i < 2; ++i)
#pragma unroll
        for (int j = 0; j < 8; ++j)
#pragma unroll
            for (int e = 0; e < 4; ++e) acc[i][j][e] = 0.0f;

    const int nch = K >> 5;
    {
        float4 pa[4], pb[4];
        loadA_p(A, lda, 0, tid, pa);
        loadB_p(B, ldb, 0, tid, pb);
        storeA_p(pa, s, tid);
        storeB_p(pb, s + 4096, tid);
    }
    __syncthreads();

    for (int c = 0; c < nch; ++c) {
        float4 pa[4], pb[4];
        const bool more = (c + 1 < nch);
        if (more) {
            loadA_p(A, lda, (c + 1) * 32, tid, pa);
            loadB_p(B, ldb, (c + 1) * 32, tid, pb);
        }
        uint32_t* As = s + (c & 1) * 8192;
        uint32_t* Bs = As + 4096;
#pragma unroll
        for (int ks = 0; ks < 4; ++ks) {
            uint32_t af[2][4];
#pragma unroll
            for (int mf = 0; mf < 2; ++mf)
                *(uint4*)af[mf] = *(const uint4*)&As[((ks * 8 + mgb + mf) * 32 + lane) * 4];
            uint32_t bf[8][2];
#pragma unroll
            for (int nf = 0; nf < 8; ++nf)
                *(uint2*)bf[nf] = *(const uint2*)&Bs[((ks * 16 + ngb + nf) * 32 + lane) * 2];
#pragma unroll
            for (int mf = 0; mf < 2; ++mf)
#pragma unroll
                for (int nf = 0; nf < 8; ++nf)
                    mma_tf32(acc[mf][nf], af[mf], bf[nf]);
        }
        if (more) {
            uint32_t* d = s + ((c + 1) & 1) * 8192;
            storeA_p(pa, d, tid);
            storeB_p(pb, d + 4096, tid);
        }
        __syncthreads();
    }
}

// ---------------- stage 1: all 4 projections, direct register epilogue ----------------
__global__ __launch_bounds__(256) void k_projAll(
    const float* __restrict__ q,  const float* __restrict__ kk, const float* __restrict__ vv,
    const float* __restrict__ pe,
    const float* __restrict__ Wq, const float* __restrict__ bq,
    const float* __restrict__ Wk, const float* __restrict__ bk,
    const float* __restrict__ Wv, const float* __restrict__ bv,
    const float* __restrict__ Wp,
    const float* __restrict__ ub, const float* __restrict__ vb)
{
    extern __shared__ char sm[];
    const int mode = blockIdx.z;
    const float* A; const float* W; const float* bias = nullptr;
    switch (mode) {
        case 0: A = q;  W = Wq; bias = bq; break;
        case 1: A = kk; W = Wk; bias = bk; break;
        case 2: A = vv; W = Wv; bias = bv; break;
        default: A = pe; W = Wp; break;
    }
    const int n0 = blockIdx.x * 128, m0 = blockIdx.y * 128;
    float acc[2][8][4];
    gemm128_core(A + (size_t)m0 * DD, DD, W + (size_t)n0 * DD, DD, DD, sm, acc);

    const int tid = threadIdx.x, wid = tid >> 5, lane = tid & 31;
    const int gr = lane >> 2, gc = (lane & 3) * 2;
    const int wm = wid & 3, wn = wid >> 2;
    const int colb = wn * 64;

    // preload per-nf bias / u / v pairs
    float2 b2[8], u2[8], v2[8];
#pragma unroll
    for (int nf = 0; nf < 8; ++nf) {
        const int n = n0 + colb + nf * 8 + gc;
        b2[nf] = bias ? *(const float2*)(bias + n) : make_float2(0.f, 0.f);
        if (mode == 0) {
            u2[nf] = *(const float2*)(ub + n);
            v2[nf] = *(const float2*)(vb + n);
        }
    }
    float* out1; float* out2 = nullptr;
    switch (mode) {
        case 0: out1 = g_Qu; out2 = g_Qv; break;
        case 1: out1 = g_Kh; break;
        case 2: out1 = g_Vh; break;
        default: out1 = g_Ph; break;
    }
#pragma unroll
    for (int mf = 0; mf < 2; ++mf) {
#pragma unroll
        for (int half = 0; half < 2; ++half) {
            const int r = wm * 32 + mf * 16 + gr + half * 8;
            const int m = m0 + r, b = m >> 11, sIdx = m & (SS - 1);
#pragma unroll
            for (int nf = 0; nf < 8; ++nf) {
                const int n = n0 + colb + nf * 8 + gc;
                const int h = n >> 6, d = n & 63;
                const size_t o = (((size_t)(b * HH + h)) * SS + sIdx) * DHH + d;
                float x0 = acc[mf][nf][half * 2 + 0] + b2[nf].x;
                float x1 = acc[mf][nf][half * 2 + 1] + b2[nf].y;
                if (mode == 0) {
                    *(float2*)(out1 + o) = make_float2(x0 + u2[nf].x, x1 + u2[nf].y);
                    *(float2*)(out2 + o) = make_float2(x0 + v2[nf].x, x1 + v2[nf].y);
                } else {
                    *(float2*)(out1 + o) = make_float2(x0, x1);
                }
            }
        }
    }
}

// ---------------- V transpose: [bh][s][d] -> [bh][d][s] ----------------
__global__ void k_transpose() {
    __shared__ float t[32][33];
    const int bh = blockIdx.z, s0 = blockIdx.x * 32, d0 = blockIdx.y * 32;
    const int tx = threadIdx.x, ty = threadIdx.y;
    for (int i = 0; i < 32; i += 8)
        t[ty + i][tx] = g_Vh[((size_t)bh * SS + s0 + ty + i) * DHH + d0 + tx];
    __syncthreads();
    for (int i = 0; i < 32; i += 8)
        g_VhT[((size_t)bh * DHH + d0 + ty + i) * SS + s0 + tx] = t[tx][ty + i];
}

// ---------------- zero the rel-shift diagonal k = q+1 ----------------
__global__ void k_zdiag() {
    int i = blockIdx.x * 256 + threadIdx.x;
    if (i >= BHH * (SS - 1)) return;
    int bh = i / (SS - 1), qq = i % (SS - 1);
    g_S1[(size_t)bh * SS * SS + (size_t)qq * SS + qq + 1] = 0.0f;
}

// ---------------- stage 2a: pos scores -> PRE-SHIFTED g_S1, direct epilogue ----------------
// Shift is linear: source (qq, j) -> linear qq*(SS+1) + j + 1 - SS (both branches).
// Valid iff lin >= 0 (only qq==0 rows clip). Pairs are column-adjacent; STG.64 when
// lin even (qq odd <=> gr odd), else 2x STG.32.
__global__ __launch_bounds__(256) void k_pos() {
    extern __shared__ char sm[];
    const int bh = blockIdx.z, k0 = blockIdx.x * 128, q0 = blockIdx.y * 128;
    float acc[2][8][4];
    gemm128_core(g_Qv + ((size_t)bh * SS + q0) * DHH, DHH,
                 g_Ph + ((size_t)bh * SS + k0) * DHH, DHH, DHH, sm, acc);

    const int tid = threadIdx.x, wid = tid >> 5, lane = tid & 31;
    const int gr = lane >> 2, gc = (lane & 3) * 2;
    const int wm = wid & 3, wn = wid >> 2;
    float* S1s = g_S1 + (size_t)bh * SS * SS;
#pragma unroll
    for (int mf = 0; mf < 2; ++mf) {
#pragma unroll
        for (int half = 0; half < 2; ++half) {
            const int r = wm * 32 + mf * 16 + gr + half * 8;
            const int qq = q0 + r;
            const int lin_base = qq * (SS + 1) + 1 - SS + k0 + wn * 64 + gc;
            if (gr & 1) {   // qq odd -> lin even -> 8B-aligned pairs
#pragma unroll
                for (int nf = 0; nf < 8; ++nf) {
                    *(float2*)(S1s + lin_base + nf * 8) =
                        make_float2(acc[mf][nf][half * 2], acc[mf][nf][half * 2 + 1]);
                }
            } else {        // scalar path (also covers qq==0 clipping)
#pragma unroll
                for (int nf = 0; nf < 8; ++nf) {
                    const int lin = lin_base + nf * 8;
                    if (lin >= 0)     S1s[lin]     = acc[mf][nf][half * 2];
                    if (lin + 1 >= 0) S1s[lin + 1] = acc[mf][nf][half * 2 + 1];
                }
            }
        }
    }
}

// ================= fused flash attention v2 (pre-shifted pos, STS.64 staging) =================
#define F2_QUA   0
#define F2_KHB   8192
#define F2_VB    12288
#define F2_PST   16384
#define F2_RS    24576
#define F2_WORDS 24832

__global__ __launch_bounds__(512, 2) void k_flash2() {
    extern __shared__ char sm[];
    uint32_t* s = (uint32_t*)sm;
    const int tid  = threadIdx.x;
    const int wid  = tid >> 5;
    const int lane = tid & 31;
    const int gr   = lane >> 2;
    const int gc   = (lane & 3) * 2;
    const int wm   = wid & 7;
    const int wn   = wid >> 3;

    const int bh = blockIdx.y, q0 = blockIdx.x * 128;
    const int b = bh >> 4, h = bh & (HH - 1);

    const float* Qbase = g_Qu + ((size_t)bh * SS + q0) * DHH;
    const float* Kbase = g_Kh + (size_t)bh * SS * DHH;
    const float* Vbase = g_VhT + (size_t)bh * DHH * SS;
    const float* S1b   = g_S1 + (size_t)bh * SS * SS;
    const float scale = 0.03125f;

    // stage Qu A-fragments (paired STS.64)
    {
        const int c4 = tid & 7, rr = tid >> 3;
        const int r = ((rr >> 3) << 4) + (rr & 7);
#pragma unroll
        for (int ch = 0; ch < 2; ++ch) {
            float4 lo = *(const float4*)(Qbase + (size_t)r * DHH + ch * 32 + c4 * 4);
            float4 hi = *(const float4*)(Qbase + (size_t)(r + 8) * DHH + ch * 32 + c4 * 4);
            uint2* d2 = (uint2*)(s + F2_QUA + ch * 4096);
            const int kstep = c4 >> 1, mg = r >> 4, laneb = (r & 7) * 4, rh = c4 & 1;
            const float l4[4] = {lo.x, lo.y, lo.z, lo.w};
            const float h4[4] = {hi.x, hi.y, hi.z, hi.w};
#pragma unroll
            for (int e = 0; e < 4; ++e)
                d2[(((kstep * 8 + mg) * 32) + laneb + e) * 2 + rh] = pack_tf32(l4[e], h4[e]);
        }
    }

    float Oacc[4][4];
#pragma unroll
    for (int nf = 0; nf < 4; ++nf)
#pragma unroll
        for (int e = 0; e < 4; ++e) Oacc[nf][e] = 0.0f;
    float rsum[2] = {0.0f, 0.0f};

    const int st_ch = tid >> 8;
    const int st_s4 = tid & 3;
    const int st_r  = (tid & 255) >> 2;
    const int st_ng = st_r >> 3, st_laneb = (st_r & 7) * 4;

    const int qg0 = q0 + wm * 16 + gr;
    const int qg1 = qg0 + 8;

    for (int t = 0; t < 32; ++t) {
        const int k0 = t * 64;
        __syncthreads();
        // ---- stage K tile ----
        {
            float4 lo = *(const float4*)(Kbase + (size_t)(k0 + st_r) * DHH + st_ch * 32 + st_s4 * 8);
            float4 hi = *(const float4*)(Kbase + (size_t)(k0 + st_r) * DHH + st_ch * 32 + st_s4 * 8 + 4);
            uint2* d2 = (uint2*)(s + F2_KHB + st_ch * 2048);
            const float l4[4] = {lo.x, lo.y, lo.z, lo.w};
            const float h4[4] = {hi.x, hi.y, hi.z, hi.w};
#pragma unroll
            for (int e = 0; e < 4; ++e)
                d2[(st_s4 * 8 + st_ng) * 32 + st_laneb + e] = pack_tf32(l4[e], h4[e]);
        }
        // ---- stage V tile ----
        {
            float4 lo = *(const float4*)(Vbase + (size_t)st_r * SS + k0 + st_ch * 32 + st_s4 * 8);
            float4 hi = *(const float4*)(Vbase + (size_t)st_r * SS + k0 + st_ch * 32 + st_s4 * 8 + 4);
            uint2* d2 = (uint2*)(s + F2_VB + st_ch * 2048);
            const float l4[4] = {lo.x, lo.y, lo.z, lo.w};
            const float h4[4] = {hi.x, hi.y, hi.z, hi.w};
#pragma unroll
            for (int e = 0; e < 4; ++e)
                d2[(st_s4 * 8 + st_ng) * 32 + st_laneb + e] = pack_tf32(l4[e], h4[e]);
        }
        __syncthreads();

        // ---- score MMA ----
        float acc[4][4];
#pragma unroll
        for (int nf = 0; nf < 4; ++nf)
#pragma unroll
            for (int e = 0; e < 4; ++e) acc[nf][e] = 0.0f;
#pragma unroll
        for (int ch = 0; ch < 2; ++ch) {
            const uint32_t* As = s + F2_QUA + ch * 4096;
            const uint32_t* Bs = s + F2_KHB + ch * 2048;
#pragma unroll
            for (int ks = 0; ks < 4; ++ks) {
                uint32_t af[4];
                *(uint4*)af = *(const uint4*)&As[((ks * 8 + wm) * 32 + lane) * 4];
                uint32_t bf[4][2];
#pragma unroll
                for (int nf = 0; nf < 4; ++nf)
                    *(uint2*)bf[nf] = *(const uint2*)&Bs[((ks * 8 + wn * 4 + nf) * 32 + lane) * 2];
#pragma unroll
                for (int nf = 0; nf < 4; ++nf)
                    mma_tf32(acc[nf], af, bf[nf]);
            }
        }

        // ---- add pre-shifted pos (contiguous float2), scale, exp, rowsum, stage P ----
        {
            const float2* pr0 = (const float2*)(S1b + (size_t)qg0 * SS + k0 + wn * 32 + gc);
            const float2* pr1 = (const float2*)(S1b + (size_t)qg1 * SS + k0 + wn * 32 + gc);
            uint2* pd = (uint2*)(s + F2_PST + wn * 4096);
#pragma unroll
            for (int nf = 0; nf < 4; ++nf) {
                const float2 a2 = pr0[nf * 4];
                const float2 b2 = pr1[nf * 4];
                float p00 = __expf((acc[nf][0] + a2.x) * scale);
                float p01 = __expf((acc[nf][1] + a2.y) * scale);
                float p10 = __expf((acc[nf][2] + b2.x) * scale);
                float p11 = __expf((acc[nf][3] + b2.y) * scale);
                rsum[0] += p00 + p01;
                rsum[1] += p10 + p11;
                const int c0 = nf * 8 + gc;
                pd[((nf * 8 + wm) * 32 + gr * 4 + (c0 & 3)) * 2 + ((c0 >> 2) & 1)] =
                    pack_tf32(p00, p10);
                const int c1 = c0 + 1;
                pd[((nf * 8 + wm) * 32 + gr * 4 + (c1 & 3)) * 2 + ((c1 >> 2) & 1)] =
                    pack_tf32(p01, p11);
            }
        }
        __syncthreads();

        // ---- PV MMA ----
#pragma unroll
        for (int ch = 0; ch < 2; ++ch) {
            const uint32_t* Ps = s + F2_PST + ch * 4096;
            const uint32_t* Vs = s + F2_VB + ch * 2048;
#pragma unroll
            for (int ks = 0; ks < 4; ++ks) {
                uint32_t af[4];
                *(uint4*)af = *(const uint4*)&Ps[((ks * 8 + wm) * 32 + lane) * 4];
                uint32_t bf[4][2];
#pragma unroll
                for (int nf = 0; nf < 4; ++nf)
                    *(uint2*)bf[nf] = *(const uint2*)&Vs[((ks * 8 + wn * 4 + nf) * 32 + lane) * 2];
#pragma unroll
                for (int nf = 0; nf < 4; ++nf)
                    mma_tf32(Oacc[nf], af, bf[nf]);
            }
        }
    }
    __syncthreads();

    // ---- reduce rowsums ----
    float* rs = (float*)(s + F2_RS);
#pragma unroll
    for (int half = 0; half < 2; ++half) {
        float v = rsum[half];
        v += __shfl_xor_sync(0xFFFFFFFF, v, 1);
        v += __shfl_xor_sync(0xFFFFFFFF, v, 2);
        if ((lane & 3) == 0)
            rs[wn * 128 + wm * 16 + gr + half * 8] = v;
    }
    __syncthreads();

    // ---- finalize ----
    {
        const int r0 = wm * 16 + gr, r1 = r0 + 8;
        const float i0 = 1.0f / (rs[r0] + rs[128 + r0]);
        const float i1 = 1.0f / (rs[r1] + rs[128 + r1]);
        __syncthreads();
        float* smfO = (float*)(s + F2_KHB);
#pragma unroll
        for (int nf = 0; nf < 4; ++nf) {
            const int c = wn * 32 + nf * 8 + gc;
            smfO[r0 * 68 + c]     = Oacc[nf][0] * i0;
            smfO[r0 * 68 + c + 1] = Oacc[nf][1] * i0;
            smfO[r1 * 68 + c]     = Oacc[nf][2] * i1;
            smfO[r1 * 68 + c + 1] = Oacc[nf][3] * i1;
        }
        __syncthreads();
#pragma unroll
        for (int it = 0; it < 4; ++it) {
            int idx = tid + it * 512;
            int r = idx >> 4, c4f = (idx & 15) * 4;
            float4 v = *(float4*)(smfO + r * 68 + c4f);
            *(float4*)(g_O + ((size_t)b * SS + q0 + r) * DD + h * 64 + c4f) = v;
        }
    }
}

// ---------------- stage 5: output projection, direct register epilogue ----------------
__global__ __launch_bounds__(256) void k_outproj(
    const float* __restrict__ Wo, const float* __restrict__ bo, float* __restrict__ out)
{
    extern __shared__ char sm[];
    const int n0 = blockIdx.x * 128, m0 = blockIdx.y * 128;
    float acc[2][8][4];
    gemm128_core(g_O + (size_t)m0 * DD, DD, Wo + (size_t)n0 * DD, DD, DD, sm, acc);

    const int tid = threadIdx.x, wid = tid >> 5, lane = tid & 31;
    const int gr = lane >> 2, gc = (lane & 3) * 2;
    const int wm = wid & 3, wn = wid >> 2;
    const int colb = wn * 64;
    float2 b2[8];
#pragma unroll
    for (int nf = 0; nf < 8; ++nf)
        b2[nf] = *(const float2*)(bo + n0 + colb + nf * 8 + gc);
#pragma unroll
    for (int mf = 0; mf < 2; ++mf) {
#pragma unroll
        for (int half = 0; half < 2; ++half) {
            const int r = wm * 32 + mf * 16 + gr + half * 8;
            float* orow = out + (size_t)(m0 + r) * DD + n0 + colb + gc;
#pragma unroll
            for (int nf = 0; nf < 8; ++nf) {
                *(float2*)(orow + nf * 8) =
                    make_float2(acc[mf][nf][half * 2] + b2[nf].x,
                                acc[mf][nf][half * 2 + 1] + b2[nf].y);
            }
        }
    }
}

// ---------------- launch ----------------
extern "C" void kernel_launch(void* const* d_in, const int* in_sizes, int n_in,
                              void* d_out, int out_size)
{
    const float* q  = (const float*)d_in[0];
    const float* k  = (const float*)d_in[1];
    const float* v  = (const float*)d_in[2];
    const float* pe = (const float*)d_in[3];
    const float* Wq = (const float*)d_in[4];
    const float* bq = (const float*)d_in[5];
    const float* Wk = (const float*)d_in[6];
    const float* bk = (const float*)d_in[7];
    const float* Wv = (const float*)d_in[8];
    const float* bv = (const float*)d_in[9];
    const float* Wp = (const float*)d_in[10];
    const float* ub = (const float*)d_in[11];
    const float* vb = (const float*)d_in[12];
    const float* Wo = (const float*)d_in[13];
    const float* bo = (const float*)d_in[14];
    float* out = (float*)d_out;

    const int S128   = 65536;                 // 2 x 32KB double-buffer stages
    const int SFLASH = F2_WORDS * 4;          // 99328 bytes
    cudaFuncSetAttribute(k_projAll, cudaFuncAttributeMaxDynamicSharedMemorySize, S128);
    cudaFuncSetAttribute(k_pos,     cudaFuncAttributeMaxDynamicSharedMemorySize, S128);
    cudaFuncSetAttribute(k_outproj, cudaFuncAttributeMaxDynamicSharedMemorySize, S128);
    cudaFuncSetAttribute(k_flash2,  cudaFuncAttributeMaxDynamicSharedMemorySize, SFLASH);

    k_projAll<<<dim3(DD / 128, MM / 128, 4), 256, S128>>>(
        q, k, v, pe, Wq, bq, Wk, bk, Wv, bv, Wp, ub, vb);

    k_transpose<<<dim3(SS / 32, DHH / 32, BHH), dim3(32, 8)>>>();

    k_zdiag<<<(BHH * (SS - 1) + 255) / 256, 256>>>();

    k_pos<<<dim3(SS / 128, SS / 128, BHH), 256, S128>>>();

    k_flash2<<<dim3(SS / 128, BHH), 512, SFLASH>>>();

    k_outproj<<<dim3(DD / 128, MM / 128), 256, S128>>>(Wo, bo, out);
}

// round 11
// speedup vs baseline: 1.5111x; 1.5111x over previous
#include <cuda_runtime.h>
#include <cstdint>

#define BB 2
#define SS 2048
#define DD 1024
#define HH 16
#define DHH 64
#define BHH 32
#define MM 4096

// ---------------- scratch ----------------
__device__ float g_Qu[(size_t)BHH * SS * DHH];
__device__ float g_Qv[(size_t)BHH * SS * DHH];
__device__ float g_Kh[(size_t)BHH * SS * DHH];
__device__ float g_Vh[(size_t)BHH * SS * DHH];
__device__ float g_VhT[(size_t)BHH * SS * DHH];   // [bh][d][s]
__device__ float g_Ph[(size_t)BHH * SS * DHH];
__device__ float g_S1[(size_t)BHH * SS * SS];     // PRE-SHIFTED pos scores
__device__ float g_O [(size_t)MM * DD];

// ---------------- mma.sync tf32 helpers ----------------
__device__ __forceinline__ uint32_t f2tf32(float f) {
    uint32_t t;
    asm("cvt.rna.tf32.f32 %0, %1;" : "=r"(t) : "f"(f));
    return t;
}
__device__ __forceinline__ void mma_tf32(float c[4], const uint32_t a[4], const uint32_t b[2]) {
    asm volatile(
        "mma.sync.aligned.m16n8k8.row.col.f32.tf32.tf32.f32 "
        "{%0,%1,%2,%3}, {%4,%5,%6,%7}, {%8,%9}, {%0,%1,%2,%3};"
        : "+f"(c[0]), "+f"(c[1]), "+f"(c[2]), "+f"(c[3])
        : "r"(a[0]), "r"(a[1]), "r"(a[2]), "r"(a[3]), "r"(b[0]), "r"(b[1]));
}
__device__ __forceinline__ uint2 pack_tf32(float lo, float hi) {
    uint2 u; u.x = f2tf32(lo); u.y = f2tf32(hi); return u;
}

// ================= paired loaders / STS.64 stores (256-thread, run_gemm) =================
__device__ __forceinline__ void loadA_p(const float* __restrict__ src, int lda,
                                        int kc, int tid, float4* pa) {
#pragma unroll
    for (int j = 0; j < 2; ++j) {
        int i2 = tid + j * 256;
        int c4 = i2 & 7, rr = i2 >> 3;
        int r = ((rr >> 3) << 4) + (rr & 7);
        pa[2 * j]     = *(const float4*)(src + (size_t)r * lda + kc + c4 * 4);
        pa[2 * j + 1] = *(const float4*)(src + (size_t)(r + 8) * lda + kc + c4 * 4);
    }
}
__device__ __forceinline__ void storeA_p(const float4* pa, uint32_t* dst, int tid) {
    uint2* d2 = (uint2*)dst;
#pragma unroll
    for (int j = 0; j < 2; ++j) {
        int i2 = tid + j * 256;
        int c4 = i2 & 7, rr = i2 >> 3;
        int r = ((rr >> 3) << 4) + (rr & 7);
        int kstep = c4 >> 1, mg = r >> 4, laneb = (r & 7) * 4, rh = c4 & 1;
        const float lo[4] = {pa[2 * j].x, pa[2 * j].y, pa[2 * j].z, pa[2 * j].w};
        const float hi[4] = {pa[2 * j + 1].x, pa[2 * j + 1].y, pa[2 * j + 1].z, pa[2 * j + 1].w};
#pragma unroll
        for (int e = 0; e < 4; ++e)
            d2[(((kstep * 8 + mg) * 32) + laneb + e) * 2 + rh] = pack_tf32(lo[e], hi[e]);
    }
}
template<int NT, int NJ>
__device__ __forceinline__ void loadB_p(const float* __restrict__ src, int ldb,
                                        int kc, int tid, float4* pb) {
#pragma unroll
    for (int j = 0; j < NJ; ++j) {
        int i2 = tid + j * 256;
        int s4 = i2 & 3, r = i2 >> 2;
        pb[2 * j]     = *(const float4*)(src + (size_t)r * ldb + kc + s4 * 8);
        pb[2 * j + 1] = *(const float4*)(src + (size_t)r * ldb + kc + s4 * 8 + 4);
    }
}
template<int NT, int NJ>
__device__ __forceinline__ void storeB_p(const float4* pb, uint32_t* dst, int tid) {
    constexpr int NG = NT / 8;
    uint2* d2 = (uint2*)dst;
#pragma unroll
    for (int j = 0; j < NJ; ++j) {
        int i2 = tid + j * 256;
        int s4 = i2 & 3, r = i2 >> 2;
        int ng = r >> 3, laneb = (r & 7) * 4;
        const float lo[4] = {pb[2 * j].x, pb[2 * j].y, pb[2 * j].z, pb[2 * j].w};
        const float hi[4] = {pb[2 * j + 1].x, pb[2 * j + 1].y, pb[2 * j + 1].z, pb[2 * j + 1].w};
#pragma unroll
        for (int e = 0; e < 4; ++e)
            d2[(s4 * NG + ng) * 32 + laneb + e] = pack_tf32(lo[e], hi[e]);
    }
}

// ================= generic tf32 GEMM core =================
template<int NT>
__device__ void run_gemm(const float* __restrict__ A, int lda,
                         const float* __restrict__ B, int ldb,
                         int K, char* sm) {
    constexpr int NJ   = NT / 64;
    constexpr int NG   = NT / 8;
    constexpr int NWN  = NT / 64;
    constexpr int NWM  = 8 / NWN;
    constexpr int MF   = 8 / NWM;
    constexpr int AW   = 4096;
    constexpr int BW   = NT * 32;
    constexpr int STW  = AW + BW;
    constexpr int PAD  = NT + 4;

    const int tid  = threadIdx.x;
    const int wid  = tid >> 5;
    const int lane = tid & 31;
    const int wm   = wid % NWM;
    const int wn   = wid / NWM;
    const int mgb  = wm * MF;
    const int ngb  = wn * 8;

    uint32_t* s = (uint32_t*)sm;
    float acc[MF][8][4];
#pragma unroll
    for (int i = 0; i < MF; ++i)
#pragma unroll
        for (int j = 0; j < 8; ++j)
#pragma unroll
            for (int e = 0; e < 4; ++e) acc[i][j][e] = 0.0f;

    const int nch = K >> 5;
    {
        float4 pa[4], pb[2 * NJ];
        loadA_p(A, lda, 0, tid, pa);
        loadB_p<NT, NJ>(B, ldb, 0, tid, pb);
        storeA_p(pa, s, tid);
        storeB_p<NT, NJ>(pb, s + AW, tid);
    }
    __syncthreads();

    for (int c = 0; c < nch; ++c) {
        float4 pa[4], pb[2 * NJ];
        const bool more = (c + 1 < nch);
        if (more) {
            loadA_p(A, lda, (c + 1) * 32, tid, pa);
            loadB_p<NT, NJ>(B, ldb, (c + 1) * 32, tid, pb);
        }
        uint32_t* As = s + (c & 1) * STW;
        uint32_t* Bs = As + AW;
#pragma unroll
        for (int ks = 0; ks < 4; ++ks) {
            uint32_t af[MF][4];
#pragma unroll
            for (int mf = 0; mf < MF; ++mf)
                *(uint4*)af[mf] = *(const uint4*)&As[((ks * 8 + mgb + mf) * 32 + lane) * 4];
            uint32_t bf[8][2];
#pragma unroll
            for (int nf = 0; nf < 8; ++nf)
                *(uint2*)bf[nf] = *(const uint2*)&Bs[((ks * NG + ngb + nf) * 32 + lane) * 2];
#pragma unroll
            for (int mf = 0; mf < MF; ++mf)
#pragma unroll
                for (int nf = 0; nf < 8; ++nf)
                    mma_tf32(acc[mf][nf], af[mf], bf[nf]);
        }
        if (more) {
            uint32_t* d = s + ((c + 1) & 1) * STW;
            storeA_p(pa, d, tid);
            storeB_p<NT, NJ>(pb, d + AW, tid);
        }
        __syncthreads();
    }

    float* smf = (float*)sm;
    const int gr = lane >> 2, gc = (lane & 3) * 2;
    const int rowb = wm * (MF * 16);
    const int colb = wn * 64;
#pragma unroll
    for (int mf = 0; mf < MF; ++mf) {
#pragma unroll
        for (int nf = 0; nf < 8; ++nf) {
            int row = rowb + mf * 16 + gr;
            int col = colb + nf * 8 + gc;
            *(float2*)(smf + row * PAD + col)       = make_float2(acc[mf][nf][0], acc[mf][nf][1]);
            *(float2*)(smf + (row + 8) * PAD + col) = make_float2(acc[mf][nf][2], acc[mf][nf][3]);
        }
    }
    __syncthreads();
}

// ---------------- stage 1: all 4 projections in one launch (z = mode) ----------------
__global__ __launch_bounds__(256) void k_projAll(
    const float* __restrict__ q,  const float* __restrict__ kk, const float* __restrict__ vv,
    const float* __restrict__ pe,
    const float* __restrict__ Wq, const float* __restrict__ bq,
    const float* __restrict__ Wk, const float* __restrict__ bk,
    const float* __restrict__ Wv, const float* __restrict__ bv,
    const float* __restrict__ Wp,
    const float* __restrict__ ub, const float* __restrict__ vb)
{
    extern __shared__ char sm[];
    const int mode = blockIdx.z;
    const float* A; const float* W; const float* bias = nullptr;
    switch (mode) {
        case 0: A = q;  W = Wq; bias = bq; break;
        case 1: A = kk; W = Wk; bias = bk; break;
        case 2: A = vv; W = Wv; bias = bv; break;
        default: A = pe; W = Wp; break;
    }
    const int n0 = blockIdx.x * 128, m0 = blockIdx.y * 128;
    run_gemm<128>(A + (size_t)m0 * DD, DD, W + (size_t)n0 * DD, DD, DD, sm);
    float* smf = (float*)sm;
    const int tid = threadIdx.x, wid = tid >> 5, lid = tid & 31;
    const int col4 = lid * 4;
    const int n = n0 + col4;
    const int h = n >> 6;
    const int d = n & 63;
    float4 bb = bias ? *(const float4*)(bias + n) : make_float4(0, 0, 0, 0);
    float4 uu = (mode == 0) ? *(const float4*)(ub + n) : make_float4(0, 0, 0, 0);
    float4 vvb = (mode == 0) ? *(const float4*)(vb + n) : make_float4(0, 0, 0, 0);
#pragma unroll
    for (int it = 0; it < 16; ++it) {
        int r = wid * 16 + it;
        float4 v = *(float4*)(smf + r * 132 + col4);
        v.x += bb.x; v.y += bb.y; v.z += bb.z; v.w += bb.w;
        int m = m0 + r, b = m >> 11, ss = m & (SS - 1);
        size_t o = (((size_t)(b * HH + h)) * SS + ss) * DHH + d;
        if (mode == 0) {
            *(float4*)(g_Qu + o) = make_float4(v.x + uu.x, v.y + uu.y, v.z + uu.z, v.w + uu.w);
            *(float4*)(g_Qv + o) = make_float4(v.x + vvb.x, v.y + vvb.y, v.z + vvb.z, v.w + vvb.w);
        } else if (mode == 1) *(float4*)(g_Kh + o) = v;
        else if (mode == 2)   *(float4*)(g_Vh + o) = v;
        else                  *(float4*)(g_Ph + o) = v;
    }
}

// ---------------- V transpose: [bh][s][d] -> [bh][d][s] ----------------
__global__ void k_transpose() {
    __shared__ float t[32][33];
    const int bh = blockIdx.z, s0 = blockIdx.x * 32, d0 = blockIdx.y * 32;
    const int tx = threadIdx.x, ty = threadIdx.y;
    for (int i = 0; i < 32; i += 8)
        t[ty + i][tx] = g_Vh[((size_t)bh * SS + s0 + ty + i) * DHH + d0 + tx];
    __syncthreads();
    for (int i = 0; i < 32; i += 8)
        g_VhT[((size_t)bh * DHH + d0 + ty + i) * SS + s0 + tx] = t[tx][ty + i];
}

// ---------------- zero the rel-shift diagonal k = q+1 ----------------
__global__ void k_zdiag() {
    int i = blockIdx.x * 256 + threadIdx.x;
    if (i >= BHH * (SS - 1)) return;
    int bh = i / (SS - 1), qq = i % (SS - 1);
    g_S1[(size_t)bh * SS * SS + (size_t)qq * SS + qq + 1] = 0.0f;
}

// ---------------- stage 2a: pos scores -> PRE-SHIFTED g_S1 ----------------
// source P[q][j] maps to: (q, j-(S-1-q)) if j >= S-1-q, else (q-1, j+q+1) [q>=1].
// Writes are row-contiguous (shift constant per row) -> coalesced scalar STG.
__global__ __launch_bounds__(256) void k_pos() {
    extern __shared__ char sm[];
    const int bh = blockIdx.z, k0 = blockIdx.x * 128, q0 = blockIdx.y * 128;
    run_gemm<128>(g_Qv + ((size_t)bh * SS + q0) * DHH, DHH,
                  g_Ph + ((size_t)bh * SS + k0) * DHH, DHH, DHH, sm);
    float* smf = (float*)sm;
    const int tid = threadIdx.x, wid = tid >> 5, lane = tid & 31;
    float* S1s = g_S1 + (size_t)bh * SS * SS;
#pragma unroll
    for (int it = 0; it < 16; ++it) {
        const int r = wid * 16 + it;
        const int qq = q0 + r;
        const int boundary = SS - 1 - qq;
#pragma unroll
        for (int c = 0; c < 4; ++c) {
            const int jl = c * 32 + lane;
            const int j  = k0 + jl;
            const float v = smf[r * 132 + jl];
            if (j >= boundary)
                S1s[(size_t)qq * SS + (j - boundary)] = v;
            else if (qq >= 1)
                S1s[(size_t)(qq - 1) * SS + (j + qq + 1)] = v;
        }
    }
}

// ================= fused flash attention v2 (pre-shifted pos, STS.64 staging) =================
#define F2_QUA   0
#define F2_KHB   8192
#define F2_VB    12288
#define F2_PST   16384
#define F2_RS    24576
#define F2_WORDS 24832

__global__ __launch_bounds__(512, 2) void k_flash2() {
    extern __shared__ char sm[];
    uint32_t* s = (uint32_t*)sm;
    const int tid  = threadIdx.x;
    const int wid  = tid >> 5;
    const int lane = tid & 31;
    const int gr   = lane >> 2;
    const int gc   = (lane & 3) * 2;
    const int wm   = wid & 7;
    const int wn   = wid >> 3;

    const int bh = blockIdx.y, q0 = blockIdx.x * 128;
    const int b = bh >> 4, h = bh & (HH - 1);

    const float* Qbase = g_Qu + ((size_t)bh * SS + q0) * DHH;
    const float* Kbase = g_Kh + (size_t)bh * SS * DHH;
    const float* Vbase = g_VhT + (size_t)bh * DHH * SS;
    const float* S1b   = g_S1 + (size_t)bh * SS * SS;
    const float scale = 0.03125f;

    // stage Qu A-fragments (paired STS.64)
    {
        const int c4 = tid & 7, rr = tid >> 3;
        const int r = ((rr >> 3) << 4) + (rr & 7);
#pragma unroll
        for (int ch = 0; ch < 2; ++ch) {
            float4 lo = *(const float4*)(Qbase + (size_t)r * DHH + ch * 32 + c4 * 4);
            float4 hi = *(const float4*)(Qbase + (size_t)(r + 8) * DHH + ch * 32 + c4 * 4);
            uint2* d2 = (uint2*)(s + F2_QUA + ch * 4096);
            const int kstep = c4 >> 1, mg = r >> 4, laneb = (r & 7) * 4, rh = c4 & 1;
            const float l4[4] = {lo.x, lo.y, lo.z, lo.w};
            const float h4[4] = {hi.x, hi.y, hi.z, hi.w};
#pragma unroll
            for (int e = 0; e < 4; ++e)
                d2[(((kstep * 8 + mg) * 32) + laneb + e) * 2 + rh] = pack_tf32(l4[e], h4[e]);
        }
    }

    float Oacc[4][4];
#pragma unroll
    for (int nf = 0; nf < 4; ++nf)
#pragma unroll
        for (int e = 0; e < 4; ++e) Oacc[nf][e] = 0.0f;
    float rsum[2] = {0.0f, 0.0f};

    const int st_ch = tid >> 8;
    const int st_s4 = tid & 3;
    const int st_r  = (tid & 255) >> 2;
    const int st_ng = st_r >> 3, st_laneb = (st_r & 7) * 4;

    const int qg0 = q0 + wm * 16 + gr;
    const int qg1 = qg0 + 8;

    for (int t = 0; t < 32; ++t) {
        const int k0 = t * 64;
        __syncthreads();
        // ---- stage K tile ----
        {
            float4 lo = *(const float4*)(Kbase + (size_t)(k0 + st_r) * DHH + st_ch * 32 + st_s4 * 8);
            float4 hi = *(const float4*)(Kbase + (size_t)(k0 + st_r) * DHH + st_ch * 32 + st_s4 * 8 + 4);
            uint2* d2 = (uint2*)(s + F2_KHB + st_ch * 2048);
            const float l4[4] = {lo.x, lo.y, lo.z, lo.w};
            const float h4[4] = {hi.x, hi.y, hi.z, hi.w};
#pragma unroll
            for (int e = 0; e < 4; ++e)
                d2[(st_s4 * 8 + st_ng) * 32 + st_laneb + e] = pack_tf32(l4[e], h4[e]);
        }
        // ---- stage V tile ----
        {
            float4 lo = *(const float4*)(Vbase + (size_t)st_r * SS + k0 + st_ch * 32 + st_s4 * 8);
            float4 hi = *(const float4*)(Vbase + (size_t)st_r * SS + k0 + st_ch * 32 + st_s4 * 8 + 4);
            uint2* d2 = (uint2*)(s + F2_VB + st_ch * 2048);
            const float l4[4] = {lo.x, lo.y, lo.z, lo.w};
            const float h4[4] = {hi.x, hi.y, hi.z, hi.w};
#pragma unroll
            for (int e = 0; e < 4; ++e)
                d2[(st_s4 * 8 + st_ng) * 32 + st_laneb + e] = pack_tf32(l4[e], h4[e]);
        }
        __syncthreads();

        // ---- score MMA ----
        float acc[4][4];
#pragma unroll
        for (int nf = 0; nf < 4; ++nf)
#pragma unroll
            for (int e = 0; e < 4; ++e) acc[nf][e] = 0.0f;
#pragma unroll
        for (int ch = 0; ch < 2; ++ch) {
            const uint32_t* As = s + F2_QUA + ch * 4096;
            const uint32_t* Bs = s + F2_KHB + ch * 2048;
#pragma unroll
            for (int ks = 0; ks < 4; ++ks) {
                uint32_t af[4];
                *(uint4*)af = *(const uint4*)&As[((ks * 8 + wm) * 32 + lane) * 4];
                uint32_t bf[4][2];
#pragma unroll
                for (int nf = 0; nf < 4; ++nf)
                    *(uint2*)bf[nf] = *(const uint2*)&Bs[((ks * 8 + wn * 4 + nf) * 32 + lane) * 2];
#pragma unroll
                for (int nf = 0; nf < 4; ++nf)
                    mma_tf32(acc[nf], af, bf[nf]);
            }
        }

        // ---- add pre-shifted pos (contiguous float2), scale, exp, rowsum, stage P ----
        {
            const float2* pr0 = (const float2*)(S1b + (size_t)qg0 * SS + k0 + wn * 32 + gc);
            const float2* pr1 = (const float2*)(S1b + (size_t)qg1 * SS + k0 + wn * 32 + gc);
            uint2* pd = (uint2*)(s + F2_PST + wn * 4096);
#pragma unroll
            for (int nf = 0; nf < 4; ++nf) {
                const float2 a2 = pr0[nf * 4];
                const float2 b2 = pr1[nf * 4];
                float p00 = __expf((acc[nf][0] + a2.x) * scale);
                float p01 = __expf((acc[nf][1] + a2.y) * scale);
                float p10 = __expf((acc[nf][2] + b2.x) * scale);
                float p11 = __expf((acc[nf][3] + b2.y) * scale);
                rsum[0] += p00 + p01;
                rsum[1] += p10 + p11;
                const int c0 = nf * 8 + gc;
                pd[((nf * 8 + wm) * 32 + gr * 4 + (c0 & 3)) * 2 + ((c0 >> 2) & 1)] =
                    pack_tf32(p00, p10);
                const int c1 = c0 + 1;
                pd[((nf * 8 + wm) * 32 + gr * 4 + (c1 & 3)) * 2 + ((c1 >> 2) & 1)] =
                    pack_tf32(p01, p11);
            }
        }
        __syncthreads();

        // ---- PV MMA ----
#pragma unroll
        for (int ch = 0; ch < 2; ++ch) {
            const uint32_t* Ps = s + F2_PST + ch * 4096;
            const uint32_t* Vs = s + F2_VB + ch * 2048;
#pragma unroll
            for (int ks = 0; ks < 4; ++ks) {
                uint32_t af[4];
                *(uint4*)af = *(const uint4*)&Ps[((ks * 8 + wm) * 32 + lane) * 4];
                uint32_t bf[4][2];
#pragma unroll
                for (int nf = 0; nf < 4; ++nf)
                    *(uint2*)bf[nf] = *(const uint2*)&Vs[((ks * 8 + wn * 4 + nf) * 32 + lane) * 2];
#pragma unroll
                for (int nf = 0; nf < 4; ++nf)
                    mma_tf32(Oacc[nf], af, bf[nf]);
            }
        }
    }
    __syncthreads();

    // ---- reduce rowsums ----
    float* rs = (float*)(s + F2_RS);
#pragma unroll
    for (int half = 0; half < 2; ++half) {
        float v = rsum[half];
        v += __shfl_xor_sync(0xFFFFFFFF, v, 1);
        v += __shfl_xor_sync(0xFFFFFFFF, v, 2);
        if ((lane & 3) == 0)
            rs[wn * 128 + wm * 16 + gr + half * 8] = v;
    }
    __syncthreads();

    // ---- finalize ----
    {
        const int r0 = wm * 16 + gr, r1 = r0 + 8;
        const float i0 = 1.0f / (rs[r0] + rs[128 + r0]);
        const float i1 = 1.0f / (rs[r1] + rs[128 + r1]);
        __syncthreads();
        float* smfO = (float*)(s + F2_KHB);
#pragma unroll
        for (int nf = 0; nf < 4; ++nf) {
            const int c = wn * 32 + nf * 8 + gc;
            *(float2*)(smfO + r0 * 68 + c) = make_float2(Oacc[nf][0] * i0, Oacc[nf][1] * i0);
            *(float2*)(smfO + r1 * 68 + c) = make_float2(Oacc[nf][2] * i1, Oacc[nf][3] * i1);
        }
        __syncthreads();
#pragma unroll
        for (int it = 0; it < 4; ++it) {
            int idx = tid + it * 512;
            int r = idx >> 4, c4f = (idx & 15) * 4;
            float4 v = *(float4*)(smfO + r * 68 + c4f);
            *(float4*)(g_O + ((size_t)b * SS + q0 + r) * DD + h * 64 + c4f) = v;
        }
    }
}

// ---------------- stage 5: output projection ----------------
__global__ __launch_bounds__(256) void k_outproj(
    const float* __restrict__ Wo, const float* __restrict__ bo, float* __restrict__ out)
{
    extern __shared__ char sm[];
    const int n0 = blockIdx.x * 128, m0 = blockIdx.y * 128;
    run_gemm<128>(g_O + (size_t)m0 * DD, DD, Wo + (size_t)n0 * DD, DD, DD, sm);
    float* smf = (float*)sm;
    const int tid = threadIdx.x, wid = tid >> 5, lid = tid & 31;
    float4 bb = *(const float4*)(bo + n0 + lid * 4);
#pragma unroll
    for (int it = 0; it < 16; ++it) {
        int r = wid * 16 + it;
        float4 v = *(float4*)(smf + r * 132 + lid * 4);
        v.x += bb.x; v.y += bb.y; v.z += bb.z; v.w += bb.w;
        *(float4*)(out + (size_t)(m0 + r) * DD + n0 + lid * 4) = v;
    }
}

// ---------------- launch ----------------
extern "C" void kernel_launch(void* const* d_in, const int* in_sizes, int n_in,
                              void* d_out, int out_size)
{
    const float* q  = (const float*)d_in[0];
    const float* k  = (const float*)d_in[1];
    const float* v  = (const float*)d_in[2];
    const float* pe = (const float*)d_in[3];
    const float* Wq = (const float*)d_in[4];
    const float* bq = (const float*)d_in[5];
    const float* Wk = (const float*)d_in[6];
    const float* bk = (const float*)d_in[7];
    const float* Wv = (const float*)d_in[8];
    const float* bv = (const float*)d_in[9];
    const float* Wp = (const float*)d_in[10];
    const float* ub = (const float*)d_in[11];
    const float* vb = (const float*)d_in[12];
    const float* Wo = (const float*)d_in[13];
    const float* bo = (const float*)d_in[14];
    float* out = (float*)d_out;

    const int S128   = 67584;
    const int SFLASH = F2_WORDS * 4;          // 99328 bytes
    cudaFuncSetAttribute(k_projAll, cudaFuncAttributeMaxDynamicSharedMemorySize, S128);
    cudaFuncSetAttribute(k_pos,     cudaFuncAttributeMaxDynamicSharedMemorySize, S128);
    cudaFuncSetAttribute(k_outproj, cudaFuncAttributeMaxDynamicSharedMemorySize, S128);
    cudaFuncSetAttribute(k_flash2,  cudaFuncAttributeMaxDynamicSharedMemorySize, SFLASH);

    k_projAll<<<dim3(DD / 128, MM / 128, 4), 256, S128>>>(
        q, k, v, pe, Wq, bq, Wk, bk, Wv, bv, Wp, ub, vb);

    k_transpose<<<dim3(SS / 32, DHH / 32, BHH), dim3(32, 8)>>>();

    k_zdiag<<<(BHH * (SS - 1) + 255) / 256, 256>>>();

    k_pos<<<dim3(SS / 128, SS / 128, BHH), 256, S128>>>();

    k_flash2<<<dim3(SS / 128, BHH), 512, SFLASH>>>();

    k_outproj<<<dim3(DD / 128, MM / 128), 256, S128>>>(Wo, bo, out);
}

// round 13
// speedup vs baseline: 2.5075x; 1.6594x over previous
#include <cuda_runtime.h>
#include <cuda_fp16.h>
#include <cstdint>

#define BB 2
#define SS 2048
#define DD 1024
#define HH 16
#define DHH 64
#define BHH 32
#define MM 4096

// ---------------- scratch ----------------
__device__ float g_Qu[(size_t)BHH * SS * DHH];
__device__ float g_Qv[(size_t)BHH * SS * DHH];
__device__ float g_Kh[(size_t)BHH * SS * DHH];
__device__ float g_Vh[(size_t)BHH * SS * DHH];
__device__ float g_VhT[(size_t)BHH * SS * DHH];   // [bh][d][s]
__device__ float g_Ph[(size_t)BHH * SS * DHH];
__device__ float g_S1[(size_t)BHH * SS * SS];     // PRE-SHIFTED pos scores
__device__ float g_O [(size_t)MM * DD];

// ---------------- fp16 mma helpers ----------------
__device__ __forceinline__ uint32_t h2(float lo, float hi) {
    __half2 h = __floats2half2_rn(lo, hi);
    return *(uint32_t*)&h;
}
__device__ __forceinline__ void mma_f16(float c[4], const uint32_t a[4], const uint32_t b[2]) {
    asm volatile(
        "mma.sync.aligned.m16n8k16.row.col.f32.f16.f16.f32 "
        "{%0,%1,%2,%3}, {%4,%5,%6,%7}, {%8,%9}, {%0,%1,%2,%3};"
        : "+f"(c[0]), "+f"(c[1]), "+f"(c[2]), "+f"(c[3])
        : "r"(a[0]), "r"(a[1]), "r"(a[2]), "r"(a[3]), "r"(b[0]), "r"(b[1]));
}

// ================= fp16 staging (256-thread run_gemm, 128x32 chunks) =================
// A smem: [kstep(2)][mg(8)][lane(32)][4 words]  (2048 words / chunk)
// B smem: [kstep(2)][ng(16)][lane(32)][2 words] (2048 words / chunk)
__device__ __forceinline__ void loadA_p(const float* __restrict__ src, int lda,
                                        int kc, int tid, float4* pa) {
#pragma unroll
    for (int j = 0; j < 2; ++j) {
        int i2 = tid + j * 256;
        int c4 = i2 & 7, rr = i2 >> 3;
        int r = ((rr >> 3) << 4) + (rr & 7);
        pa[2 * j]     = *(const float4*)(src + (size_t)r * lda + kc + c4 * 4);
        pa[2 * j + 1] = *(const float4*)(src + (size_t)(r + 8) * lda + kc + c4 * 4);
    }
}
__device__ __forceinline__ void storeA_h(const float4* pa, uint32_t* dst, int tid) {
    uint2* d2 = (uint2*)dst;
#pragma unroll
    for (int j = 0; j < 2; ++j) {
        int i2 = tid + j * 256;
        int c4 = i2 & 7, rr = i2 >> 3;
        int r = ((rr >> 3) << 4) + (rr & 7);
        int kstep = c4 >> 2, cc = c4 & 3, ch = cc >> 1, tigb = (cc & 1) * 2;
        int base = ((kstep * 8 + (r >> 4)) * 32) + (r & 7) * 4 + tigb;
        const float4 lo = pa[2 * j], hi = pa[2 * j + 1];
        uint2 w0, w1;
        w0.x = h2(lo.x, lo.y); w0.y = h2(hi.x, hi.y);
        w1.x = h2(lo.z, lo.w); w1.y = h2(hi.z, hi.w);
        d2[base * 2 + ch]       = w0;
        d2[(base + 1) * 2 + ch] = w1;
    }
}
__device__ __forceinline__ void loadB_h(const float* __restrict__ src, int ldb,
                                        int kc, int tid, float4* pb) {
#pragma unroll
    for (int j = 0; j < 2; ++j) {
        int p = tid + j * 256;
        int r = p >> 2, sub = p & 3;
        int kb = kc + (sub >> 1) * 16 + (sub & 1) * 4;
        pb[2 * j]     = *(const float4*)(src + (size_t)r * ldb + kb);
        pb[2 * j + 1] = *(const float4*)(src + (size_t)r * ldb + kb + 8);
    }
}
__device__ __forceinline__ void storeB_h(const float4* pb, uint32_t* dst, int tid) {
    uint2* d2 = (uint2*)dst;
#pragma unroll
    for (int j = 0; j < 2; ++j) {
        int p = tid + j * 256;
        int r = p >> 2, sub = p & 3;
        int kstep = sub >> 1, q = sub & 1;
        int base = ((kstep * 16 + (r >> 3)) * 32) + (r & 7) * 4 + q * 2;
        const float4 a = pb[2 * j], b = pb[2 * j + 1];
        uint2 w0, w1;
        w0.x = h2(a.x, a.y); w0.y = h2(b.x, b.y);
        w1.x = h2(a.z, a.w); w1.y = h2(b.z, b.w);
        d2[base]     = w0;
        d2[base + 1] = w1;
    }
}

// ================= fp16 GEMM core (C[128x128], 256 threads) =================
__device__ void run_gemm(const float* __restrict__ A, int lda,
                         const float* __restrict__ B, int ldb,
                         int K, char* sm) {
    constexpr int PAD = 132;
    const int tid  = threadIdx.x;
    const int wid  = tid >> 5;
    const int lane = tid & 31;
    const int wm   = wid & 3;
    const int wn   = wid >> 2;
    const int mgb  = wm * 2;
    const int ngb  = wn * 8;

    uint32_t* s = (uint32_t*)sm;
    float acc[2][8][4];
#pragma unroll
    for (int i = 0; i < 2; ++i)
#pragma unroll
        for (int j = 0; j < 8; ++j)
#pragma unroll
            for (int e = 0; e < 4; ++e) acc[i][j][e] = 0.0f;

    const int nch = K >> 5;
    {
        float4 pa[4], pb[4];
        loadA_p(A, lda, 0, tid, pa);
        loadB_h(B, ldb, 0, tid, pb);
        storeA_h(pa, s, tid);
        storeB_h(pb, s + 2048, tid);
    }
    __syncthreads();

    for (int c = 0; c < nch; ++c) {
        float4 pa[4], pb[4];
        const bool more = (c + 1 < nch);
        if (more) {
            loadA_p(A, lda, (c + 1) * 32, tid, pa);
            loadB_h(B, ldb, (c + 1) * 32, tid, pb);
        }
        uint32_t* As = s + (c & 1) * 4096;
        uint32_t* Bs = As + 2048;
#pragma unroll
        for (int ks = 0; ks < 2; ++ks) {
            uint32_t af[2][4];
#pragma unroll
            for (int mf = 0; mf < 2; ++mf)
                *(uint4*)af[mf] = *(const uint4*)&As[((ks * 8 + mgb + mf) * 32 + lane) * 4];
            uint32_t bf[8][2];
#pragma unroll
            for (int nf = 0; nf < 8; ++nf)
                *(uint2*)bf[nf] = *(const uint2*)&Bs[((ks * 16 + ngb + nf) * 32 + lane) * 2];
#pragma unroll
            for (int mf = 0; mf < 2; ++mf)
#pragma unroll
                for (int nf = 0; nf < 8; ++nf)
                    mma_f16(acc[mf][nf], af[mf], bf[nf]);
        }
        if (more) {
            uint32_t* d = s + ((c + 1) & 1) * 4096;
            storeA_h(pa, d, tid);
            storeB_h(pb, d + 2048, tid);
        }
        __syncthreads();
    }

    // stage accumulators -> smem float [128][PAD]
    float* smf = (float*)sm;
    const int gr = lane >> 2, gc = (lane & 3) * 2;
#pragma unroll
    for (int mf = 0; mf < 2; ++mf) {
#pragma unroll
        for (int nf = 0; nf < 8; ++nf) {
            int row = wm * 32 + mf * 16 + gr;
            int col = wn * 64 + nf * 8 + gc;
            *(float2*)(smf + row * PAD + col)       = make_float2(acc[mf][nf][0], acc[mf][nf][1]);
            *(float2*)(smf + (row + 8) * PAD + col) = make_float2(acc[mf][nf][2], acc[mf][nf][3]);
        }
    }
    __syncthreads();
}

// ---------------- stage 1: all 4 projections in one launch (z = mode) ----------------
__global__ __launch_bounds__(256) void k_projAll(
    const float* __restrict__ q,  const float* __restrict__ kk, const float* __restrict__ vv,
    const float* __restrict__ pe,
    const float* __restrict__ Wq, const float* __restrict__ bq,
    const float* __restrict__ Wk, const float* __restrict__ bk,
    const float* __restrict__ Wv, const float* __restrict__ bv,
    const float* __restrict__ Wp,
    const float* __restrict__ ub, const float* __restrict__ vb)
{
    extern __shared__ char sm[];
    const int mode = blockIdx.z;
    const float* A; const float* W; const float* bias = nullptr;
    switch (mode) {
        case 0: A = q;  W = Wq; bias = bq; break;
        case 1: A = kk; W = Wk; bias = bk; break;
        case 2: A = vv; W = Wv; bias = bv; break;
        default: A = pe; W = Wp; break;
    }
    const int n0 = blockIdx.x * 128, m0 = blockIdx.y * 128;
    run_gemm(A + (size_t)m0 * DD, DD, W + (size_t)n0 * DD, DD, DD, sm);
    float* smf = (float*)sm;
    const int tid = threadIdx.x, wid = tid >> 5, lid = tid & 31;
    const int col4 = lid * 4;
    const int n = n0 + col4;
    const int h = n >> 6;
    const int d = n & 63;
    float4 bb = bias ? *(const float4*)(bias + n) : make_float4(0, 0, 0, 0);
    float4 uu = (mode == 0) ? *(const float4*)(ub + n) : make_float4(0, 0, 0, 0);
    float4 vvb = (mode == 0) ? *(const float4*)(vb + n) : make_float4(0, 0, 0, 0);
#pragma unroll
    for (int it = 0; it < 16; ++it) {
        int r = wid * 16 + it;
        float4 v = *(float4*)(smf + r * 132 + col4);
        v.x += bb.x; v.y += bb.y; v.z += bb.z; v.w += bb.w;
        int m = m0 + r, b = m >> 11, ss = m & (SS - 1);
        size_t o = (((size_t)(b * HH + h)) * SS + ss) * DHH + d;
        if (mode == 0) {
            *(float4*)(g_Qu + o) = make_float4(v.x + uu.x, v.y + uu.y, v.z + uu.z, v.w + uu.w);
            *(float4*)(g_Qv + o) = make_float4(v.x + vvb.x, v.y + vvb.y, v.z + vvb.z, v.w + vvb.w);
        } else if (mode == 1) *(float4*)(g_Kh + o) = v;
        else if (mode == 2)   *(float4*)(g_Vh + o) = v;
        else                  *(float4*)(g_Ph + o) = v;
    }
}

// ---------------- V transpose: [bh][s][d] -> [bh][d][s] ----------------
__global__ void k_transpose() {
    __shared__ float t[32][33];
    const int bh = blockIdx.z, s0 = blockIdx.x * 32, d0 = blockIdx.y * 32;
    const int tx = threadIdx.x, ty = threadIdx.y;
    for (int i = 0; i < 32; i += 8)
        t[ty + i][tx] = g_Vh[((size_t)bh * SS + s0 + ty + i) * DHH + d0 + tx];
    __syncthreads();
    for (int i = 0; i < 32; i += 8)
        g_VhT[((size_t)bh * DHH + d0 + ty + i) * SS + s0 + tx] = t[tx][ty + i];
}

// ---------------- zero the rel-shift diagonal k = q+1 ----------------
__global__ void k_zdiag() {
    int i = blockIdx.x * 256 + threadIdx.x;
    if (i >= BHH * (SS - 1)) return;
    int bh = i / (SS - 1), qq = i % (SS - 1);
    g_S1[(size_t)bh * SS * SS + (size_t)qq * SS + qq + 1] = 0.0f;
}

// ---------------- stage 2a: pos scores -> PRE-SHIFTED g_S1 ----------------
__global__ __launch_bounds__(256) void k_pos() {
    extern __shared__ char sm[];
    const int bh = blockIdx.z, k0 = blockIdx.x * 128, q0 = blockIdx.y * 128;
    run_gemm(g_Qv + ((size_t)bh * SS + q0) * DHH, DHH,
             g_Ph + ((size_t)bh * SS + k0) * DHH, DHH, DHH, sm);
    float* smf = (float*)sm;
    const int tid = threadIdx.x, wid = tid >> 5, lane = tid & 31;
    float* S1s = g_S1 + (size_t)bh * SS * SS;
#pragma unroll
    for (int it = 0; it < 16; ++it) {
        const int r = wid * 16 + it;
        const int qq = q0 + r;
        const int boundary = SS - 1 - qq;
#pragma unroll
        for (int c = 0; c < 4; ++c) {
            const int jl = c * 32 + lane;
            const int j  = k0 + jl;
            const float v = smf[r * 132 + jl];
            if (j >= boundary)
                S1s[(size_t)qq * SS + (j - boundary)] = v;
            else if (qq >= 1)
                S1s[(size_t)(qq - 1) * SS + (j + qq + 1)] = v;
        }
    }
}

// ================= fused flash attention (fp16 MMA, pre-shifted pos) =================
// 512 threads (16 warps), q-tile = 128, BK = 64.
// Smem words: QuA[4096] | K[2048] | V[2048] | P[4096] | rs[256] = 12544 words (50 KB)
#define F2_QUA   0
#define F2_KHB   4096
#define F2_VB    6144
#define F2_PST   8192
#define F2_RS    12288
#define F2_WORDS 12544

__global__ __launch_bounds__(512, 2) void k_flash2() {
    extern __shared__ char sm[];
    uint32_t* s = (uint32_t*)sm;
    const int tid  = threadIdx.x;
    const int wid  = tid >> 5;
    const int lane = tid & 31;
    const int gr   = lane >> 2;
    const int gc   = (lane & 3) * 2;
    const int wm   = wid & 7;
    const int wn   = wid >> 3;

    const int bh = blockIdx.y, q0 = blockIdx.x * 128;
    const int b = bh >> 4, h = bh & (HH - 1);

    const float* Qbase = g_Qu + ((size_t)bh * SS + q0) * DHH;
    const float* Kbase = g_Kh + (size_t)bh * SS * DHH;
    const float* Vbase = g_VhT + (size_t)bh * DHH * SS;
    const float* S1b   = g_S1 + (size_t)bh * SS * SS;
    const float scale = 0.03125f;

    // stage Qu A-fragments for K=64 (4 ksteps), paired STS.64
    {
        uint2* d2q = (uint2*)(s + F2_QUA);
#pragma unroll
        for (int j = 0; j < 2; ++j) {
            int i2 = tid + j * 512;
            int c4 = i2 & 15, rr = i2 >> 4;
            int r = ((rr >> 3) << 4) + (rr & 7);
            int kstep = c4 >> 2, cc = c4 & 3, ch = cc >> 1, tigb = (cc & 1) * 2;
            float4 lo = *(const float4*)(Qbase + (size_t)r * DHH + c4 * 4);
            float4 hi = *(const float4*)(Qbase + (size_t)(r + 8) * DHH + c4 * 4);
            int base = ((kstep * 8 + (r >> 4)) * 32) + (r & 7) * 4 + tigb;
            uint2 w0, w1;
            w0.x = h2(lo.x, lo.y); w0.y = h2(hi.x, hi.y);
            w1.x = h2(lo.z, lo.w); w1.y = h2(hi.z, hi.w);
            d2q[base * 2 + ch]       = w0;
            d2q[(base + 1) * 2 + ch] = w1;
        }
    }

    float Oacc[4][4];
#pragma unroll
    for (int nf = 0; nf < 4; ++nf)
#pragma unroll
        for (int e = 0; e < 4; ++e) Oacc[nf][e] = 0.0f;
    float rsum[2] = {0.0f, 0.0f};

    // staging coords: one (k, k+8)-pair per thread; tiles are 64 rows x 64 cols
    const int st_n  = tid >> 3;          // 0..63 row
    const int st_sub = tid & 7;
    const int st_ks = st_sub >> 1, st_q = st_sub & 1;
    const int st_kc = st_ks * 16 + st_q * 4;
    const int st_base = ((st_ks * 8 + (st_n >> 3)) * 32) + (st_n & 7) * 4 + st_q * 2;

    const int qg0 = q0 + wm * 16 + gr;
    const int qg1 = qg0 + 8;

    for (int t = 0; t < 32; ++t) {
        const int k0 = t * 64;
        __syncthreads();   // prior PV done -> safe to overwrite K/V/P
        // ---- stage K tile (B-frags): rows = kv index, cols = d ----
        {
            const float* src = Kbase + (size_t)(k0 + st_n) * DHH + st_kc;
            float4 a = *(const float4*)(src);
            float4 c = *(const float4*)(src + 8);
            uint2* d2 = (uint2*)(s + F2_KHB);
            uint2 w0, w1;
            w0.x = h2(a.x, a.y); w0.y = h2(c.x, c.y);
            w1.x = h2(a.z, a.w); w1.y = h2(c.z, c.w);
            d2[st_base]     = w0;
            d2[st_base + 1] = w1;
        }
        // ---- stage V tile (B-frags): rows = d, cols = kv window ----
        {
            const float* src = Vbase + (size_t)st_n * SS + k0 + st_kc;
            float4 a = *(const float4*)(src);
            float4 c = *(const float4*)(src + 8);
            uint2* d2 = (uint2*)(s + F2_VB);
            uint2 w0, w1;
            w0.x = h2(a.x, a.y); w0.y = h2(c.x, c.y);
            w1.x = h2(a.z, a.w); w1.y = h2(c.z, c.w);
            d2[st_base]     = w0;
            d2[st_base + 1] = w1;
        }
        __syncthreads();   // K/V visible

        // ---- score MMA: acc = Qu[wm*16..] . K[wn*32..]^T (4 ksteps of 16) ----
        float acc[4][4];
#pragma unroll
        for (int nf = 0; nf < 4; ++nf)
#pragma unroll
            for (int e = 0; e < 4; ++e) acc[nf][e] = 0.0f;
#pragma unroll
        for (int ks = 0; ks < 4; ++ks) {
            uint32_t af[4];
            *(uint4*)af = *(const uint4*)&s[F2_QUA + ((ks * 8 + wm) * 32 + lane) * 4];
            uint32_t bf[4][2];
#pragma unroll
            for (int nf = 0; nf < 4; ++nf)
                *(uint2*)bf[nf] = *(const uint2*)&s[F2_KHB + ((ks * 8 + wn * 4 + nf) * 32 + lane) * 2];
#pragma unroll
            for (int nf = 0; nf < 4; ++nf)
                mma_f16(acc[nf], af, bf[nf]);
        }

        // ---- pos add (contiguous float2), scale, exp, rowsum; P -> A-frags (1 STS.64/nf) ----
        {
            const float2* pr0 = (const float2*)(S1b + (size_t)qg0 * SS + k0 + wn * 32 + gc);
            const float2* pr1 = (const float2*)(S1b + (size_t)qg1 * SS + k0 + wn * 32 + gc);
            uint2* pd = (uint2*)(s + F2_PST);
#pragma unroll
            for (int nf = 0; nf < 4; ++nf) {
                const float2 a2 = pr0[nf * 4];
                const float2 b2 = pr1[nf * 4];
                float p00 = __expf((acc[nf][0] + a2.x) * scale);
                float p01 = __expf((acc[nf][1] + a2.y) * scale);
                float p10 = __expf((acc[nf][2] + b2.x) * scale);
                float p11 = __expf((acc[nf][3] + b2.y) * scale);
                rsum[0] += p00 + p01;
                rsum[1] += p10 + p11;
                const int kstep = wn * 2 + (nf >> 1);
                const int ch = nf & 1;
                uint2 w;
                w.x = h2(p00, p01);
                w.y = h2(p10, p11);
                pd[(((kstep * 8 + wm) * 32) + gr * 4 + (lane & 3)) * 2 + ch] = w;
            }
        }
        __syncthreads();   // P visible

        // ---- PV MMA: Oacc += P[wm*16..] . V (4 ksteps of 16) ----
#pragma unroll
        for (int ks = 0; ks < 4; ++ks) {
            uint32_t af[4];
            *(uint4*)af = *(const uint4*)&s[F2_PST + ((ks * 8 + wm) * 32 + lane) * 4];
            uint32_t bf[4][2];
#pragma unroll
            for (int nf = 0; nf < 4; ++nf)
                *(uint2*)bf[nf] = *(const uint2*)&s[F2_VB + ((ks * 8 + wn * 4 + nf) * 32 + lane) * 2];
#pragma unroll
            for (int nf = 0; nf < 4; ++nf)
                mma_f16(Oacc[nf], af, bf[nf]);
        }
    }
    __syncthreads();

    // ---- reduce rowsums: quad shuffle, then cross-warp over wn ----
    float* rs = (float*)(s + F2_RS);
#pragma unroll
    for (int half = 0; half < 2; ++half) {
        float v = rsum[half];
        v += __shfl_xor_sync(0xFFFFFFFF, v, 1);
        v += __shfl_xor_sync(0xFFFFFFFF, v, 2);
        if ((lane & 3) == 0)
            rs[wn * 128 + wm * 16 + gr + half * 8] = v;
    }
    __syncthreads();

    // ---- finalize: O / l -> smem staging [128][68] at offset 0 (8704 words, in-bounds) ----
    {
        const int r0 = wm * 16 + gr, r1 = r0 + 8;
        const float i0 = 1.0f / (rs[r0] + rs[128 + r0]);
        const float i1 = 1.0f / (rs[r1] + rs[128 + r1]);
        __syncthreads();   // rs read by all before smem reuse
        float* smfO = (float*)s;   // QuA/K/V/P regions are dead; rs at 12288 > 8704 untouched
#pragma unroll
        for (int nf = 0; nf < 4; ++nf) {
            const int c = wn * 32 + nf * 8 + gc;
            *(float2*)(smfO + r0 * 68 + c) = make_float2(Oacc[nf][0] * i0, Oacc[nf][1] * i0);
            *(float2*)(smfO + r1 * 68 + c) = make_float2(Oacc[nf][2] * i1, Oacc[nf][3] * i1);
        }
        __syncthreads();
#pragma unroll
        for (int it = 0; it < 4; ++it) {
            int idx = tid + it * 512;
            int r = idx >> 4, c4f = (idx & 15) * 4;
            float4 v = *(float4*)(smfO + r * 68 + c4f);
            *(float4*)(g_O + ((size_t)b * SS + q0 + r) * DD + h * 64 + c4f) = v;
        }
    }
}

// ---------------- stage 5: output projection ----------------
__global__ __launch_bounds__(256) void k_outproj(
    const float* __restrict__ Wo, const float* __restrict__ bo, float* __restrict__ out)
{
    extern __shared__ char sm[];
    const int n0 = blockIdx.x * 128, m0 = blockIdx.y * 128;
    run_gemm(g_O + (size_t)m0 * DD, DD, Wo + (size_t)n0 * DD, DD, DD, sm);
    float* smf = (float*)sm;
    const int tid = threadIdx.x, wid = tid >> 5, lid = tid & 31;
    float4 bb = *(const float4*)(bo + n0 + lid * 4);
#pragma unroll
    for (int it = 0; it < 16; ++it) {
        int r = wid * 16 + it;
        float4 v = *(float4*)(smf + r * 132 + lid * 4);
        v.x += bb.x; v.y += bb.y; v.z += bb.z; v.w += bb.w;
        *(float4*)(out + (size_t)(m0 + r) * DD + n0 + lid * 4) = v;
    }
}

// ---------------- launch ----------------
extern "C" void kernel_launch(void* const* d_in, const int* in_sizes, int n_in,
                              void* d_out, int out_size)
{
    const float* q  = (const float*)d_in[0];
    const float* k  = (const float*)d_in[1];
    const float* v  = (const float*)d_in[2];
    const float* pe = (const float*)d_in[3];
    const float* Wq = (const float*)d_in[4];
    const float* bq = (const float*)d_in[5];
    const float* Wk = (const float*)d_in[6];
    const float* bk = (const float*)d_in[7];
    const float* Wv = (const float*)d_in[8];
    const float* bv = (const float*)d_in[9];
    const float* Wp = (const float*)d_in[10];
    const float* ub = (const float*)d_in[11];
    const float* vb = (const float*)d_in[12];
    const float* Wo = (const float*)d_in[13];
    const float* bo = (const float*)d_in[14];
    float* out = (float*)d_out;

    const int S128   = 67584;                 // epilogue staging dominates (128*132*4)
    const int SFLASH = F2_WORDS * 4;          // 50176 bytes
    cudaFuncSetAttribute(k_projAll, cudaFuncAttributeMaxDynamicSharedMemorySize, S128);
    cudaFuncSetAttribute(k_pos,     cudaFuncAttributeMaxDynamicSharedMemorySize, S128);
    cudaFuncSetAttribute(k_outproj, cudaFuncAttributeMaxDynamicSharedMemorySize, S128);
    cudaFuncSetAttribute(k_flash2,  cudaFuncAttributeMaxDynamicSharedMemorySize, SFLASH);

    k_projAll<<<dim3(DD / 128, MM / 128, 4), 256, S128>>>(
        q, k, v, pe, Wq, bq, Wk, bk, Wv, bv, Wp, ub, vb);

    k_transpose<<<dim3(SS / 32, DHH / 32, BHH), dim3(32, 8)>>>();

    k_zdiag<<<(BHH * (SS - 1) + 255) / 256, 256>>>();

    k_pos<<<dim3(SS / 128, SS / 128, BHH), 256, S128>>>();

    k_flash2<<<dim3(SS / 128, BHH), 512, SFLASH>>>();

    k_outproj<<<dim3(DD / 128, MM / 128), 256, S128>>>(Wo, bo, out);
}

// round 14
// speedup vs baseline: 2.6386x; 1.0523x over previous
#include <cuda_runtime.h>
#include <cuda_fp16.h>
#include <cstdint>

#define BB 2
#define SS 2048
#define DD 1024
#define HH 16
#define DHH 64
#define BHH 32
#define MM 4096

// ---------------- scratch ----------------
__device__ float g_Qu[(size_t)BHH * SS * DHH];
__device__ float g_Qv[(size_t)BHH * SS * DHH];
__device__ float g_Kh[(size_t)BHH * SS * DHH];
__device__ float g_VhT[(size_t)BHH * SS * DHH];   // [bh][d][s]  (written directly by projAll)
__device__ float g_Ph[(size_t)BHH * SS * DHH];
__device__ __half g_S1h[(size_t)BHH * SS * SS];   // PRE-SHIFTED pos scores (fp16)
__device__ float g_O [(size_t)MM * DD];

// ---------------- fp16 mma helpers ----------------
__device__ __forceinline__ uint32_t h2(float lo, float hi) {
    __half2 h = __floats2half2_rn(lo, hi);
    return *(uint32_t*)&h;
}
__device__ __forceinline__ void mma_f16(float c[4], const uint32_t a[4], const uint32_t b[2]) {
    asm volatile(
        "mma.sync.aligned.m16n8k16.row.col.f32.f16.f16.f32 "
        "{%0,%1,%2,%3}, {%4,%5,%6,%7}, {%8,%9}, {%0,%1,%2,%3};"
        : "+f"(c[0]), "+f"(c[1]), "+f"(c[2]), "+f"(c[3])
        : "r"(a[0]), "r"(a[1]), "r"(a[2]), "r"(a[3]), "r"(b[0]), "r"(b[1]));
}

// ================= fp16 staging (256-thread gemm_core, 128x32 chunks) =================
__device__ __forceinline__ void loadA_p(const float* __restrict__ src, int lda,
                                        int kc, int tid, float4* pa) {
#pragma unroll
    for (int j = 0; j < 2; ++j) {
        int i2 = tid + j * 256;
        int c4 = i2 & 7, rr = i2 >> 3;
        int r = ((rr >> 3) << 4) + (rr & 7);
        pa[2 * j]     = *(const float4*)(src + (size_t)r * lda + kc + c4 * 4);
        pa[2 * j + 1] = *(const float4*)(src + (size_t)(r + 8) * lda + kc + c4 * 4);
    }
}
__device__ __forceinline__ void storeA_h(const float4* pa, uint32_t* dst, int tid) {
    uint2* d2 = (uint2*)dst;
#pragma unroll
    for (int j = 0; j < 2; ++j) {
        int i2 = tid + j * 256;
        int c4 = i2 & 7, rr = i2 >> 3;
        int r = ((rr >> 3) << 4) + (rr & 7);
        int kstep = c4 >> 2, cc = c4 & 3, ch = cc >> 1, tigb = (cc & 1) * 2;
        int base = ((kstep * 8 + (r >> 4)) * 32) + (r & 7) * 4 + tigb;
        const float4 lo = pa[2 * j], hi = pa[2 * j + 1];
        uint2 w0, w1;
        w0.x = h2(lo.x, lo.y); w0.y = h2(hi.x, hi.y);
        w1.x = h2(lo.z, lo.w); w1.y = h2(hi.z, hi.w);
        d2[base * 2 + ch]       = w0;
        d2[(base + 1) * 2 + ch] = w1;
    }
}
__device__ __forceinline__ void loadB_h(const float* __restrict__ src, int ldb,
                                        int kc, int tid, float4* pb) {
#pragma unroll
    for (int j = 0; j < 2; ++j) {
        int p = tid + j * 256;
        int r = p >> 2, sub = p & 3;
        int kb = kc + (sub >> 1) * 16 + (sub & 1) * 4;
        pb[2 * j]     = *(const float4*)(src + (size_t)r * ldb + kb);
        pb[2 * j + 1] = *(const float4*)(src + (size_t)r * ldb + kb + 8);
    }
}
__device__ __forceinline__ void storeB_h(const float4* pb, uint32_t* dst, int tid) {
    uint2* d2 = (uint2*)dst;
#pragma unroll
    for (int j = 0; j < 2; ++j) {
        int p = tid + j * 256;
        int r = p >> 2, sub = p & 3;
        int kstep = sub >> 1, q = sub & 1;
        int base = ((kstep * 16 + (r >> 3)) * 32) + (r & 7) * 4 + q * 2;
        const float4 a = pb[2 * j], b = pb[2 * j + 1];
        uint2 w0, w1;
        w0.x = h2(a.x, a.y); w0.y = h2(b.x, b.y);
        w1.x = h2(a.z, a.w); w1.y = h2(b.z, b.w);
        d2[base]     = w0;
        d2[base + 1] = w1;
    }
}

// ================= fp16 GEMM mainloop (C[128x128] in registers) =================
// Thread (wm=wid%4, wn=wid/4): rows wm*32+mf*16+{gr,gr+8}, cols wn*64+nf*8+{gc,gc+1}.
__device__ __forceinline__ void gemm_core(const float* __restrict__ A, int lda,
                                          const float* __restrict__ B, int ldb,
                                          int K, char* sm, float acc[2][8][4]) {
    const int tid  = threadIdx.x;
    const int wid  = tid >> 5;
    const int lane = tid & 31;
    const int mgb  = (wid & 3) * 2;
    const int ngb  = (wid >> 2) * 8;

    uint32_t* s = (uint32_t*)sm;
#pragma unroll
    for (int i = 0; i < 2; ++i)
#pragma unroll
        for (int j = 0; j < 8; ++j)
#pragma unroll
            for (int e = 0; e < 4; ++e) acc[i][j][e] = 0.0f;

    const int nch = K >> 5;
    {
        float4 pa[4], pb[4];
        loadA_p(A, lda, 0, tid, pa);
        loadB_h(B, ldb, 0, tid, pb);
        storeA_h(pa, s, tid);
        storeB_h(pb, s + 2048, tid);
    }
    __syncthreads();

    for (int c = 0; c < nch; ++c) {
        float4 pa[4], pb[4];
        const bool more = (c + 1 < nch);
        if (more) {
            loadA_p(A, lda, (c + 1) * 32, tid, pa);
            loadB_h(B, ldb, (c + 1) * 32, tid, pb);
        }
        uint32_t* As = s + (c & 1) * 4096;
        uint32_t* Bs = As + 2048;
#pragma unroll
        for (int ks = 0; ks < 2; ++ks) {
            uint32_t af[2][4];
#pragma unroll
            for (int mf = 0; mf < 2; ++mf)
                *(uint4*)af[mf] = *(const uint4*)&As[((ks * 8 + mgb + mf) * 32 + lane) * 4];
            uint32_t bf[8][2];
#pragma unroll
            for (int nf = 0; nf < 8; ++nf)
                *(uint2*)bf[nf] = *(const uint2*)&Bs[((ks * 16 + ngb + nf) * 32 + lane) * 2];
#pragma unroll
            for (int mf = 0; mf < 2; ++mf)
#pragma unroll
                for (int nf = 0; nf < 8; ++nf)
                    mma_f16(acc[mf][nf], af[mf], bf[nf]);
        }
        if (more) {
            uint32_t* d = s + ((c + 1) & 1) * 4096;
            storeA_h(pa, d, tid);
            storeB_h(pb, d + 2048, tid);
        }
        __syncthreads();
    }
}

// normal staging: smem float [128][132], row-major
__device__ __forceinline__ void stage_normal(float acc[2][8][4], char* sm) {
    float* smf = (float*)sm;
    const int tid = threadIdx.x, wid = tid >> 5, lane = tid & 31;
    const int gr = lane >> 2, gc = (lane & 3) * 2;
    const int wm = wid & 3, wn = wid >> 2;
#pragma unroll
    for (int mf = 0; mf < 2; ++mf) {
#pragma unroll
        for (int nf = 0; nf < 8; ++nf) {
            int row = wm * 32 + mf * 16 + gr;
            int col = wn * 64 + nf * 8 + gc;
            *(float2*)(smf + row * 132 + col)       = make_float2(acc[mf][nf][0], acc[mf][nf][1]);
            *(float2*)(smf + (row + 8) * 132 + col) = make_float2(acc[mf][nf][2], acc[mf][nf][3]);
        }
    }
    __syncthreads();
}

// transposed staging (for V^T): smem float [col(128)][132], bias added in regs
__device__ __forceinline__ void stage_transposed(float acc[2][8][4], char* sm,
                                                 const float* __restrict__ bias, int n0) {
    float* smf = (float*)sm;
    const int tid = threadIdx.x, wid = tid >> 5, lane = tid & 31;
    const int gr = lane >> 2, gc = (lane & 3) * 2;
    const int wm = wid & 3, wn = wid >> 2;
#pragma unroll
    for (int nf = 0; nf < 8; ++nf) {
        const int cc = wn * 64 + nf * 8 + gc;
        float2 b2 = *(const float2*)(bias + n0 + cc);
#pragma unroll
        for (int mf = 0; mf < 2; ++mf) {
            const int row0 = wm * 32 + mf * 16 + gr;
            smf[cc * 132 + row0]           = acc[mf][nf][0] + b2.x;
            smf[(cc + 1) * 132 + row0]     = acc[mf][nf][1] + b2.y;
            smf[cc * 132 + row0 + 8]       = acc[mf][nf][2] + b2.x;
            smf[(cc + 1) * 132 + row0 + 8] = acc[mf][nf][3] + b2.y;
        }
    }
    __syncthreads();
}

// ---------------- stage 1: all 4 projections in one launch (z = mode) ----------------
// mode 2 (V) writes g_VhT directly (transposed), eliminating the transpose kernel.
__global__ __launch_bounds__(256) void k_projAll(
    const float* __restrict__ q,  const float* __restrict__ kk, const float* __restrict__ vv,
    const float* __restrict__ pe,
    const float* __restrict__ Wq, const float* __restrict__ bq,
    const float* __restrict__ Wk, const float* __restrict__ bk,
    const float* __restrict__ Wv, const float* __restrict__ bv,
    const float* __restrict__ Wp,
    const float* __restrict__ ub, const float* __restrict__ vb)
{
    extern __shared__ char sm[];
    const int mode = blockIdx.z;
    const float* A; const float* W; const float* bias = nullptr;
    switch (mode) {
        case 0: A = q;  W = Wq; bias = bq; break;
        case 1: A = kk; W = Wk; bias = bk; break;
        case 2: A = vv; W = Wv; bias = bv; break;
        default: A = pe; W = Wp; break;
    }
    const int n0 = blockIdx.x * 128, m0 = blockIdx.y * 128;
    float acc[2][8][4];
    gemm_core(A + (size_t)m0 * DD, DD, W + (size_t)n0 * DD, DD, DD, sm, acc);

    const int tid = threadIdx.x, wid = tid >> 5, lid = tid & 31;

    if (mode == 2) {
        stage_transposed(acc, sm, bias, n0);
        float* smf = (float*)sm;
        const int b = m0 >> 11, s0 = m0 & (SS - 1);
#pragma unroll
        for (int j = 0; j < 16; ++j) {
            const int c_loc = wid * 16 + j;
            const int n = n0 + c_loc;
            const int h = n >> 6, d = n & 63;
            float4 v = *(float4*)(smf + c_loc * 132 + lid * 4);
            *(float4*)(g_VhT + (((size_t)(b * HH + h)) * DHH + d) * SS + s0 + lid * 4) = v;
        }
        return;
    }

    stage_normal(acc, sm);
    float* smf = (float*)sm;
    const int col4 = lid * 4;
    const int n = n0 + col4;
    const int h = n >> 6;
    const int d = n & 63;
    float4 bb = bias ? *(const float4*)(bias + n) : make_float4(0, 0, 0, 0);
    float4 uu = (mode == 0) ? *(const float4*)(ub + n) : make_float4(0, 0, 0, 0);
    float4 vvb = (mode == 0) ? *(const float4*)(vb + n) : make_float4(0, 0, 0, 0);
#pragma unroll
    for (int it = 0; it < 16; ++it) {
        int r = wid * 16 + it;
        float4 v = *(float4*)(smf + r * 132 + col4);
        v.x += bb.x; v.y += bb.y; v.z += bb.z; v.w += bb.w;
        int m = m0 + r, b = m >> 11, ss = m & (SS - 1);
        size_t o = (((size_t)(b * HH + h)) * SS + ss) * DHH + d;
        if (mode == 0) {
            *(float4*)(g_Qu + o) = make_float4(v.x + uu.x, v.y + uu.y, v.z + uu.z, v.w + uu.w);
            *(float4*)(g_Qv + o) = make_float4(v.x + vvb.x, v.y + vvb.y, v.z + vvb.z, v.w + vvb.w);
        } else if (mode == 1) *(float4*)(g_Kh + o) = v;
        else                  *(float4*)(g_Ph + o) = v;
    }
}

// ---------------- zero the rel-shift diagonal k = q+1 ----------------
__global__ void k_zdiag() {
    int i = blockIdx.x * 256 + threadIdx.x;
    if (i >= BHH * (SS - 1)) return;
    int bh = i / (SS - 1), qq = i % (SS - 1);
    g_S1h[(size_t)bh * SS * SS + (size_t)qq * SS + qq + 1] = __float2half(0.0f);
}

// ---------------- stage 2a: pos scores -> PRE-SHIFTED fp16 g_S1h ----------------
__global__ __launch_bounds__(256) void k_pos() {
    extern __shared__ char sm[];
    const int bh = blockIdx.z, k0 = blockIdx.x * 128, q0 = blockIdx.y * 128;
    float acc[2][8][4];
    gemm_core(g_Qv + ((size_t)bh * SS + q0) * DHH, DHH,
              g_Ph + ((size_t)bh * SS + k0) * DHH, DHH, DHH, sm, acc);
    stage_normal(acc, sm);
    float* smf = (float*)sm;
    const int tid = threadIdx.x, wid = tid >> 5, lane = tid & 31;
    __half* S1s = g_S1h + (size_t)bh * SS * SS;
#pragma unroll
    for (int it = 0; it < 16; ++it) {
        const int r = wid * 16 + it;
        const int qq = q0 + r;
        const int boundary = SS - 1 - qq;
#pragma unroll
        for (int c = 0; c < 4; ++c) {
            const int jl = c * 32 + lane;
            const int j  = k0 + jl;
            const __half v = __float2half(smf[r * 132 + jl]);
            if (j >= boundary)
                S1s[(size_t)qq * SS + (j - boundary)] = v;
            else if (qq >= 1)
                S1s[(size_t)(qq - 1) * SS + (j + qq + 1)] = v;
        }
    }
}

// ================= fused flash attention (fp16 MMA, fp16 pre-shifted pos) =================
// 512 threads (16 warps), q-tile = 128, BK = 64.
// Smem words: QuA[4096] | K[2048] | V[2048] | P[4096] | rs[256] = 12544 words (50 KB)
#define F2_QUA   0
#define F2_KHB   4096
#define F2_VB    6144
#define F2_PST   8192
#define F2_RS    12288
#define F2_WORDS 12544

__global__ __launch_bounds__(512, 2) void k_flash2() {
    extern __shared__ char sm[];
    uint32_t* s = (uint32_t*)sm;
    const int tid  = threadIdx.x;
    const int wid  = tid >> 5;
    const int lane = tid & 31;
    const int gr   = lane >> 2;
    const int gc   = (lane & 3) * 2;
    const int wm   = wid & 7;
    const int wn   = wid >> 3;

    const int bh = blockIdx.y, q0 = blockIdx.x * 128;
    const int b = bh >> 4, h = bh & (HH - 1);

    const float* Qbase = g_Qu + ((size_t)bh * SS + q0) * DHH;
    const float* Kbase = g_Kh + (size_t)bh * SS * DHH;
    const float* Vbase = g_VhT + (size_t)bh * DHH * SS;
    const __half* S1b  = g_S1h + (size_t)bh * SS * SS;
    const float scale = 0.03125f;

    // stage Qu A-fragments for K=64 (4 ksteps), paired STS.64
    {
        uint2* d2q = (uint2*)(s + F2_QUA);
#pragma unroll
        for (int j = 0; j < 2; ++j) {
            int i2 = tid + j * 512;
            int c4 = i2 & 15, rr = i2 >> 4;
            int r = ((rr >> 3) << 4) + (rr & 7);
            int kstep = c4 >> 2, cc = c4 & 3, ch = cc >> 1, tigb = (cc & 1) * 2;
            float4 lo = *(const float4*)(Qbase + (size_t)r * DHH + c4 * 4);
            float4 hi = *(const float4*)(Qbase + (size_t)(r + 8) * DHH + c4 * 4);
            int base = ((kstep * 8 + (r >> 4)) * 32) + (r & 7) * 4 + tigb;
            uint2 w0, w1;
            w0.x = h2(lo.x, lo.y); w0.y = h2(hi.x, hi.y);
            w1.x = h2(lo.z, lo.w); w1.y = h2(hi.z, hi.w);
            d2q[base * 2 + ch]       = w0;
            d2q[(base + 1) * 2 + ch] = w1;
        }
    }

    float Oacc[4][4];
#pragma unroll
    for (int nf = 0; nf < 4; ++nf)
#pragma unroll
        for (int e = 0; e < 4; ++e) Oacc[nf][e] = 0.0f;
    float rsum[2] = {0.0f, 0.0f};

    const int st_n  = tid >> 3;
    const int st_sub = tid & 7;
    const int st_ks = st_sub >> 1, st_q = st_sub & 1;
    const int st_kc = st_ks * 16 + st_q * 4;
    const int st_base = ((st_ks * 8 + (st_n >> 3)) * 32) + (st_n & 7) * 4 + st_q * 2;

    const int qg0 = q0 + wm * 16 + gr;
    const int qg1 = qg0 + 8;

    for (int t = 0; t < 32; ++t) {
        const int k0 = t * 64;
        __syncthreads();
        // ---- stage K tile ----
        {
            const float* src = Kbase + (size_t)(k0 + st_n) * DHH + st_kc;
            float4 a = *(const float4*)(src);
            float4 c = *(const float4*)(src + 8);
            uint2* d2 = (uint2*)(s + F2_KHB);
            uint2 w0, w1;
            w0.x = h2(a.x, a.y); w0.y = h2(c.x, c.y);
            w1.x = h2(a.z, a.w); w1.y = h2(c.z, c.w);
            d2[st_base]     = w0;
            d2[st_base + 1] = w1;
        }
        // ---- stage V tile ----
        {
            const float* src = Vbase + (size_t)st_n * SS + k0 + st_kc;
            float4 a = *(const float4*)(src);
            float4 c = *(const float4*)(src + 8);
            uint2* d2 = (uint2*)(s + F2_VB);
            uint2 w0, w1;
            w0.x = h2(a.x, a.y); w0.y = h2(c.x, c.y);
            w1.x = h2(a.z, a.w); w1.y = h2(c.z, c.w);
            d2[st_base]     = w0;
            d2[st_base + 1] = w1;
        }
        __syncthreads();

        // ---- score MMA ----
        float acc[4][4];
#pragma unroll
        for (int nf = 0; nf < 4; ++nf)
#pragma unroll
            for (int e = 0; e < 4; ++e) acc[nf][e] = 0.0f;
#pragma unroll
        for (int ks = 0; ks < 4; ++ks) {
            uint32_t af[4];
            *(uint4*)af = *(const uint4*)&s[F2_QUA + ((ks * 8 + wm) * 32 + lane) * 4];
            uint32_t bf[4][2];
#pragma unroll
            for (int nf = 0; nf < 4; ++nf)
                *(uint2*)bf[nf] = *(const uint2*)&s[F2_KHB + ((ks * 8 + wn * 4 + nf) * 32 + lane) * 2];
#pragma unroll
            for (int nf = 0; nf < 4; ++nf)
                mma_f16(acc[nf], af, bf[nf]);
        }

        // ---- pos add (half2 loads), scale, exp, rowsum; P -> A-frags (1 STS.64/nf) ----
        {
            const __half2* pr0 = (const __half2*)(S1b + (size_t)qg0 * SS + k0 + wn * 32 + gc);
            const __half2* pr1 = (const __half2*)(S1b + (size_t)qg1 * SS + k0 + wn * 32 + gc);
            uint2* pd = (uint2*)(s + F2_PST);
#pragma unroll
            for (int nf = 0; nf < 4; ++nf) {
                const float2 a2 = __half22float2(pr0[nf * 4]);
                const float2 b2 = __half22float2(pr1[nf * 4]);
                float p00 = __expf((acc[nf][0] + a2.x) * scale);
                float p01 = __expf((acc[nf][1] + a2.y) * scale);
                float p10 = __expf((acc[nf][2] + b2.x) * scale);
                float p11 = __expf((acc[nf][3] + b2.y) * scale);
                rsum[0] += p00 + p01;
                rsum[1] += p10 + p11;
                const int kstep = wn * 2 + (nf >> 1);
                const int ch = nf & 1;
                uint2 w;
                w.x = h2(p00, p01);
                w.y = h2(p10, p11);
                pd[(((kstep * 8 + wm) * 32) + gr * 4 + (lane & 3)) * 2 + ch] = w;
            }
        }
        __syncthreads();

        // ---- PV MMA ----
#pragma unroll
        for (int ks = 0; ks < 4; ++ks) {
            uint32_t af[4];
            *(uint4*)af = *(const uint4*)&s[F2_PST + ((ks * 8 + wm) * 32 + lane) * 4];
            uint32_t bf[4][2];
#pragma unroll
            for (int nf = 0; nf < 4; ++nf)
                *(uint2*)bf[nf] = *(const uint2*)&s[F2_VB + ((ks * 8 + wn * 4 + nf) * 32 + lane) * 2];
#pragma unroll
            for (int nf = 0; nf < 4; ++nf)
                mma_f16(Oacc[nf], af, bf[nf]);
        }
    }
    __syncthreads();

    // ---- reduce rowsums ----
    float* rs = (float*)(s + F2_RS);
#pragma unroll
    for (int half = 0; half < 2; ++half) {
        float v = rsum[half];
        v += __shfl_xor_sync(0xFFFFFFFF, v, 1);
        v += __shfl_xor_sync(0xFFFFFFFF, v, 2);
        if ((lane & 3) == 0)
            rs[wn * 128 + wm * 16 + gr + half * 8] = v;
    }
    __syncthreads();

    // ---- finalize: O / l -> smem staging [128][68] at offset 0 ----
    {
        const int r0 = wm * 16 + gr, r1 = r0 + 8;
        const float i0 = 1.0f / (rs[r0] + rs[128 + r0]);
        const float i1 = 1.0f / (rs[r1] + rs[128 + r1]);
        __syncthreads();
        float* smfO = (float*)s;
#pragma unroll
        for (int nf = 0; nf < 4; ++nf) {
            const int c = wn * 32 + nf * 8 + gc;
            *(float2*)(smfO + r0 * 68 + c) = make_float2(Oacc[nf][0] * i0, Oacc[nf][1] * i0);
            *(float2*)(smfO + r1 * 68 + c) = make_float2(Oacc[nf][2] * i1, Oacc[nf][3] * i1);
        }
        __syncthreads();
#pragma unroll
        for (int it = 0; it < 4; ++it) {
            int idx = tid + it * 512;
            int r = idx >> 4, c4f = (idx & 15) * 4;
            float4 v = *(float4*)(smfO + r * 68 + c4f);
            *(float4*)(g_O + ((size_t)b * SS + q0 + r) * DD + h * 64 + c4f) = v;
        }
    }
}

// ---------------- stage 5: output projection ----------------
__global__ __launch_bounds__(256) void k_outproj(
    const float* __restrict__ Wo, const float* __restrict__ bo, float* __restrict__ out)
{
    extern __shared__ char sm[];
    const int n0 = blockIdx.x * 128, m0 = blockIdx.y * 128;
    float acc[2][8][4];
    gemm_core(g_O + (size_t)m0 * DD, DD, Wo + (size_t)n0 * DD, DD, DD, sm, acc);
    stage_normal(acc, sm);
    float* smf = (float*)sm;
    const int tid = threadIdx.x, wid = tid >> 5, lid = tid & 31;
    float4 bb = *(const float4*)(bo + n0 + lid * 4);
#pragma unroll
    for (int it = 0; it < 16; ++it) {
        int r = wid * 16 + it;
        float4 v = *(float4*)(smf + r * 132 + lid * 4);
        v.x += bb.x; v.y += bb.y; v.z += bb.z; v.w += bb.w;
        *(float4*)(out + (size_t)(m0 + r) * DD + n0 + lid * 4) = v;
    }
}

// ---------------- launch ----------------
extern "C" void kernel_launch(void* const* d_in, const int* in_sizes, int n_in,
                              void* d_out, int out_size)
{
    const float* q  = (const float*)d_in[0];
    const float* k  = (const float*)d_in[1];
    const float* v  = (const float*)d_in[2];
    const float* pe = (const float*)d_in[3];
    const float* Wq = (const float*)d_in[4];
    const float* bq = (const float*)d_in[5];
    const float* Wk = (const float*)d_in[6];
    const float* bk = (const float*)d_in[7];
    const float* Wv = (const float*)d_in[8];
    const float* bv = (const float*)d_in[9];
    const float* Wp = (const float*)d_in[10];
    const float* ub = (const float*)d_in[11];
    const float* vb = (const float*)d_in[12];
    const float* Wo = (const float*)d_in[13];
    const float* bo = (const float*)d_in[14];
    float* out = (float*)d_out;

    const int S128   = 67584;                 // staging [128][132] floats
    const int SFLASH = F2_WORDS * 4;          // 50176 bytes
    cudaFuncSetAttribute(k_projAll, cudaFuncAttributeMaxDynamicSharedMemorySize, S128);
    cudaFuncSetAttribute(k_pos,     cudaFuncAttributeMaxDynamicSharedMemorySize, S128);
    cudaFuncSetAttribute(k_outproj, cudaFuncAttributeMaxDynamicSharedMemorySize, S128);
    cudaFuncSetAttribute(k_flash2,  cudaFuncAttributeMaxDynamicSharedMemorySize, SFLASH);

    k_projAll<<<dim3(DD / 128, MM / 128, 4), 256, S128>>>(
        q, k, v, pe, Wq, bq, Wk, bk, Wv, bv, Wp, ub, vb);

    k_zdiag<<<(BHH * (SS - 1) + 255) / 256, 256>>>();

    k_pos<<<dim3(SS / 128, SS / 128, BHH), 256, S128>>>();

    k_flash2<<<dim3(SS / 128, BHH), 512, SFLASH>>>();

    k_outproj<<<dim3(DD / 128, MM / 128), 256, S128>>>(Wo, bo, out);
}